// round 8
// baseline (speedup 1.0000x reference)
#include <cuda_runtime.h>
#include <math.h>
#include <stdint.h>

// ---------------- problem constants ----------------
#define NB   64
#define NPG  20
#define NN   1280
#define NE   24320
#define NP   12160          // unordered pairs = NE/2
#define HD   512
#define NLY  6
#define TD   256
#define NA   100
#define EINR 2313
#define TWO_PI_F 6.2831853071795864769f

// packed weight layout per layer (floats)
#define OFF_SD 0            // 512 x 1024  (src|dst merged)
#define OFF_FE 524288       // 768 x 512   (rows 0..383 = sin, 384..767 = cos)
#define OFF_E2 917504       // 512 x 512
#define OFF_N1 1179648      // 1024 x 512
#define OFF_N2 1703936      // 512 x 512
#define WLS    1966080

// ---------------- scratch ----------------
__device__ float d_wtf [(size_t)NLY * WLS];
__device__ float d_wsm [51200 + 262144];
__device__ float d_ltl [NB * 9];
__device__ int   d_pinf[NP * 4];
__device__ float d_fdP [NP * 3];
__device__ float d_udP [NP * 3];
__device__ float d_sinP[(size_t)NP * 384];
__device__ float d_cosP[(size_t)NP * 384];
__device__ float d_S   [(size_t)NP * HD];
__device__ float d_gbias[NLY * NB * HD];
__device__ float d_wnl [128 * HD];
__device__ float d_tvec[HD];
__device__ float d_h   [NN * HD];
__device__ float d_hn  [NN * HD];
__device__ float d_ns  [NN * 1024];
__device__ float d_act1[(size_t)NE * HD];
__device__ float d_cat [NN * 2 * HD];
__device__ float d_t1  [NN * HD];
__device__ float d_pool[NB * 2 * HD];

__device__ __forceinline__ float siluf(float x) { return x / (1.0f + expf(-x)); }

__device__ __forceinline__ float f2tf(float x) {
    unsigned u;
    asm("cvt.rna.tf32.f32 %0, %1;" : "=r"(u) : "f"(x));
    return __uint_as_float(u);
}

__device__ __forceinline__ void mma4(float* d, const float* a, const float* b) {
    asm volatile(
        "mma.sync.aligned.m16n8k8.row.col.f32.tf32.tf32.f32 "
        "{%0,%1,%2,%3},{%4,%5,%6,%7},{%8,%9},{%0,%1,%2,%3};\n"
        : "+f"(d[0]), "+f"(d[1]), "+f"(d[2]), "+f"(d[3])
        : "r"(__float_as_uint(a[0])), "r"(__float_as_uint(a[1])),
          "r"(__float_as_uint(a[2])), "r"(__float_as_uint(a[3])),
          "r"(__float_as_uint(b[0])), "r"(__float_as_uint(b[1])));
}

__device__ __forceinline__ void cp16(uint32_t smem, const void* gptr, bool pred) {
    int sz = pred ? 16 : 0;
    asm volatile("cp.async.cg.shared.global [%0], [%1], 16, %2;\n"
                 :: "r"(smem), "l"(gptr), "r"(sz));
}
#define CP_COMMIT() asm volatile("cp.async.commit_group;\n")
#define CP_WAIT1()  asm volatile("cp.async.wait_group 1;\n")

// smem element-offset helpers within a 16-K sub-block (R4-proven swizzle)
__device__ __forceinline__ int aoff(int r, int k) {
    return r * 16 + ((((k >> 2) ^ ((r >> 1) & 3)) << 2) | (k & 3));
}
__device__ __forceinline__ int boff(int k, int n) {
    return k * 128 + ((((n >> 2) ^ ((k & 3) << 1)) << 2) | (n & 3));
}

#define ST_FLOATS 4096                       // per-stage floats for A (=B)
#define SMEM_BYTES (3 * 2 * ST_FLOATS * 4)   // 96 KB

// ================= TF32 cp.async GEMM, 128x128 tile, K=32/stage ===========
// MODE 0: C = acc ; 1: C = silu(acc+bias) ; 3: C += silu(acc+bias)
// MODE 4: pair epilogue (writes both directed edges into act1)
// MODE 5: e2 + fused aggregation: atomicAdd(cat[node], silu(acc+bias)/19)
template<int MODE, int RND>
__global__ void __launch_bounds__(256, 2)
tcgemm(int M, int N, int K,
       const float* __restrict__ A, int lda,
       const float* __restrict__ B, int ldb,
       const float* __restrict__ bias,
       float* __restrict__ C, int ldc,
       const int* __restrict__ ei, const int* __restrict__ e2g,
       const float* __restrict__ ud, const float* __restrict__ W0,
       const float* __restrict__ gb, const float* __restrict__ nsd)
{
    extern __shared__ float smem[];
    float* sAs = smem;                       // 3 stages x 4096
    float* sBs = smem + 3 * ST_FLOATS;       // 3 stages x 4096

    const int tid  = threadIdx.x;
    const int lane = tid & 31, wid = tid >> 5;
    const int wm   = wid & 1,  wn  = wid >> 1;
    const int g    = lane >> 2, tg = lane & 3;
    const int bm   = blockIdx.y * 128, bn = blockIdx.x * 128;

    const int ar0 = tid >> 2,          as0 = tid & 3;
    const int ar1 = (tid + 256) >> 2,  as1 = tid & 3;
    const int bk0 = tid >> 5,          bg0 = tid & 31;
    const int bk1 = bk0 + 8,           bg1 = bg0;

    uint32_t sAb = (uint32_t)__cvta_generic_to_shared(sAs);
    uint32_t sBb = (uint32_t)__cvta_generic_to_shared(sBs);
    const uint32_t dA0 = (uint32_t)(ar0 * 16 + ((as0 ^ ((ar0 >> 1) & 3)) << 2)) * 4;
    const uint32_t dA1 = (uint32_t)(ar1 * 16 + ((as1 ^ ((ar1 >> 1) & 3)) << 2)) * 4;
    const uint32_t dB0 = (uint32_t)(bk0 * 128 + ((bg0 ^ ((bk0 & 3) << 1)) << 2)) * 4;
    const uint32_t dB1 = (uint32_t)(bk1 * 128 + ((bg1 ^ ((bk1 & 3) << 1)) << 2)) * 4;
    const bool pa0 = (bm + ar0) < M;
    const bool pa1 = (bm + ar1) < M;

    auto issue = [&](int st, int kt) {
        uint32_t sa = sAb + st * (ST_FLOATS * 4);
        uint32_t sb = sBb + st * (ST_FLOATS * 4);
#pragma unroll
        for (int h = 0; h < 2; h++) {
            int kh = kt + h * 16;
            uint32_t ho = (uint32_t)h * 8192;
            cp16(sa + ho + dA0, A + (size_t)(bm + ar0) * lda + kh + (as0 << 2), pa0);
            cp16(sa + ho + dA1, A + (size_t)(bm + ar1) * lda + kh + (as1 << 2), pa1);
            cp16(sb + ho + dB0, B + (size_t)(kh + bk0) * ldb + bn + (bg0 << 2), true);
            cp16(sb + ho + dB1, B + (size_t)(kh + bk1) * ldb + bn + (bg1 << 2), true);
        }
    };

    float acc[4][4][4];
#pragma unroll
    for (int i = 0; i < 4; i++)
#pragma unroll
        for (int j = 0; j < 4; j++)
#pragma unroll
            for (int r = 0; r < 4; r++) acc[i][j][r] = 0.f;

    const int T = K >> 5;
    issue(0, 0); CP_COMMIT();
    if (T > 1) issue(1, 32);
    CP_COMMIT();

    for (int it = 0; it < T; ++it) {
        CP_WAIT1();
        __syncthreads();
        if (it + 2 < T) issue((it + 2) % 3, (it + 2) << 5);
        CP_COMMIT();

        const float* sa = sAs + (it % 3) * ST_FLOATS;
        const float* sb = sBs + (it % 3) * ST_FLOATS;
#pragma unroll
        for (int ks = 0; ks < 4; ++ks) {
            const float* sah = sa + (ks >> 1) * 2048;
            const float* sbh = sb + (ks >> 1) * 2048;
            const int k0 = (ks & 1) * 8 + tg, k1 = k0 + 4;
            float a[4][4], b[4][2];
#pragma unroll
            for (int mi = 0; mi < 4; ++mi) {
                int r0 = wm * 64 + mi * 16 + g;
                a[mi][0] = sah[aoff(r0,     k0)];
                a[mi][1] = sah[aoff(r0 + 8, k0)];
                a[mi][2] = sah[aoff(r0,     k1)];
                a[mi][3] = sah[aoff(r0 + 8, k1)];
            }
#pragma unroll
            for (int ni = 0; ni < 4; ++ni) {
                int n = wn * 32 + ni * 8 + g;
                b[ni][0] = sbh[boff(k0, n)];
                b[ni][1] = sbh[boff(k1, n)];
            }
#pragma unroll
            for (int mi = 0; mi < 4; ++mi)
#pragma unroll
                for (int ni = 0; ni < 4; ++ni)
                    mma4(acc[mi][ni], a[mi], b[ni]);
        }
    }

    // epilogue
    const int mbase = bm + wm * 64;
    const int nbase = bn + wn * 32;
#pragma unroll
    for (int im = 0; im < 4; ++im) {
#pragma unroll
        for (int rh = 0; rh < 2; ++rh) {
            int m = mbase + im * 16 + rh * 8 + g;
            if (m >= M) continue;
            int ig = 0, jg = 0, ef = 0, er = 0, gph = 0, node = 0;
            float u0 = 0.f, u1 = 0.f, u2 = 0.f;
            if (MODE == 4) {
                const int4 pv = ((const int4*)ei)[m];
                ig = pv.x; jg = pv.y; ef = pv.z; er = pv.w;
                gph = ig / NPG;
                u0 = ud[m * 3 + 0]; u1 = ud[m * 3 + 1]; u2 = ud[m * 3 + 2];
            }
            if (MODE == 5) node = m / (NPG - 1);
#pragma unroll
            for (int ni = 0; ni < 4; ++ni) {
                int n = nbase + ni * 8 + tg * 2;
                float v0 = acc[im][ni][rh * 2 + 0];
                float v1 = acc[im][ni][rh * 2 + 1];
                if (MODE == 4) {
                    size_t sm = (size_t)m * HD + n;
                    float S0 = bias[sm], S1 = bias[sm + 1];
                    size_t go = (size_t)gph * HD + n;
                    float w0 = u0 * W0[n]     + u1 * W0[HD + n]     + u2 * W0[2 * HD + n];
                    float w1 = u0 * W0[n + 1] + u1 * W0[HD + n + 1] + u2 * W0[2 * HD + n + 1];
                    float b0 = v0 + gb[go], b1 = v1 + gb[go + 1];
                    size_t io = (size_t)ig * 1024 + n;
                    size_t jo = (size_t)jg * 1024 + n;
                    float zf0 = b0 + S0 + nsd[io]     + nsd[jo + 512]     + w0;
                    float zf1 = b1 + S1 + nsd[io + 1] + nsd[jo + 512 + 1] + w1;
                    float zr0 = b0 - S0 + nsd[jo]     + nsd[io + 512]     - w0;
                    float zr1 = b1 - S1 + nsd[jo + 1] + nsd[io + 512 + 1] - w1;
                    float* Cf = C + (size_t)ef * ldc + n;
                    float* Cr = C + (size_t)er * ldc + n;
                    Cf[0] = f2tf(siluf(zf0)); Cf[1] = f2tf(siluf(zf1));
                    Cr[0] = f2tf(siluf(zr0)); Cr[1] = f2tf(siluf(zr1));
                } else if (MODE == 5) {
                    float o0 = siluf(v0 + bias[n]) * (1.0f / (float)(NPG - 1));
                    float o1 = siluf(v1 + bias[n + 1]) * (1.0f / (float)(NPG - 1));
                    float* Cp = C + (size_t)node * 1024 + 512 + n;
                    atomicAdd(Cp,     o0);
                    atomicAdd(Cp + 1, o1);
                } else {
                    float* Cp = C + (size_t)m * ldc + n;
                    float o0, o1;
                    if (MODE == 0) { o0 = v0; o1 = v1; }
                    else if (MODE == 1) {
                        o0 = siluf(v0 + bias[n]); o1 = siluf(v1 + bias[n + 1]);
                    } else {  // MODE 3
                        o0 = Cp[0] + siluf(v0 + bias[n]);
                        o1 = Cp[1] + siluf(v1 + bias[n + 1]);
                    }
                    if (RND) { o0 = f2tf(o0); o1 = f2tf(o1); }
                    Cp[0] = o0; Cp[1] = o1;
                }
            }
        }
    }
}

// ---------------- weight pack + round ----------------
__global__ void pack_weights(const float* __restrict__ We1, const float* __restrict__ We2,
                             const float* __restrict__ Wn1, const float* __restrict__ Wn2,
                             float* __restrict__ out)
{
    size_t idx = (size_t)blockIdx.x * blockDim.x + threadIdx.x;
    if (idx >= (size_t)NLY * WLS) return;
    int l = (int)(idx / WLS);
    size_t r = idx - (size_t)l * WLS;
    float v;
    if (r < OFF_FE) {
        int k = (int)(r >> 10), c = (int)(r & 1023);
        int srow = (c < 512) ? (3 + k) : (515 + k);
        v = We1[((size_t)l * EINR + srow) * HD + (c & 511)];
    } else if (r < OFF_E2) {
        size_t q = r - OFF_FE;
        v = We1[((size_t)l * EINR + 1033 + (q >> 9)) * HD + (q & 511)];
    } else if (r < OFF_N1) {
        v = We2[(size_t)l * HD * HD + (r - OFF_E2)];
    } else if (r < OFF_N2) {
        v = Wn1[(size_t)l * 2 * HD * HD + (r - OFF_N1)];
    } else {
        v = Wn2[(size_t)l * HD * HD + (r - OFF_N2)];
    }
    out[idx] = f2tf(v);
}

__global__ void pack_small(const float* __restrict__ Wnode, const float* __restrict__ Wlat,
                           float* __restrict__ out)
{
    int idx = blockIdx.x * blockDim.x + threadIdx.x;
    if (idx >= 51200 + 262144) return;
    float v = (idx < 51200) ? Wnode[idx] : Wlat[idx - 51200];
    out[idx] = f2tf(v);
}

// ---------------- lattice ----------------
__global__ void lattice_kernel(const float* __restrict__ lp, float* __restrict__ ltl)
{
    int b = blockIdx.x * blockDim.x + threadIdx.x;
    if (b >= NB) return;
    const float LMn[3] = {1.575442910194397f, 1.7017393112182617f, 1.9781638383865356f};
    const float LSd[3] = {0.24437622725963593f, 0.26526379585266113f, 0.3535512685775757f};
    float len[3], ang[3];
#pragma unroll
    for (int i = 0; i < 3; i++) len[i] = expf(lp[b * 6 + i] * LSd[i] + LMn[i]);
#pragma unroll
    for (int i = 0; i < 3; i++) {
        float x  = lp[b * 6 + 3 + i];
        float sg = 1.f / (1.f + expf(-x));
        ang[i]   = (59.9f + 60.2f * sg) * 0.017453292519943295f;
    }
    float c0 = cosf(ang[0]), c1 = cosf(ang[1]), c2 = cosf(ang[2]);
    float s0 = sinf(ang[0]), s1 = sinf(ang[1]);
    float val = (c0 * c1 - c2) / (s0 * s1);
    val = fminf(1.f, fmaxf(-1.f, val));
    float gs = acosf(val);
    float L[3][3];
    L[0][0] = len[0] * s1;             L[0][1] = 0.f;                    L[0][2] = len[0] * c1;
    L[1][0] = -len[1] * s0 * cosf(gs); L[1][1] = len[1] * s0 * sinf(gs); L[1][2] = len[1] * c0;
    L[2][0] = 0.f;                     L[2][1] = 0.f;                    L[2][2] = len[2];
#pragma unroll
    for (int i = 0; i < 3; i++)
#pragma unroll
        for (int j = 0; j < 3; j++)
            ltl[b * 9 + i * 3 + j] = L[i][0] * L[j][0] + L[i][1] * L[j][1] + L[i][2] * L[j][2];
}

// ---------------- pair index generation ----------------
__global__ void pairgen_kernel(int* __restrict__ pinf)
{
    int p = blockIdx.x * blockDim.x + threadIdx.x;
    if (p >= NP) return;
    int g = p / 190, pl = p - g * 190;
    int i = 0, rem = pl;
    while (rem >= (NPG - 1) - i) { rem -= (NPG - 1) - i; i++; }
    int j = i + 1 + rem;
    int ig = g * NPG + i, jg = g * NPG + j;
    int4 v;
    v.x = ig; v.y = jg;
    v.z = ig * (NPG - 1) + (j - 1);
    v.w = jg * (NPG - 1) + i;
    ((int4*)pinf)[p] = v;
}

// ---------------- per-pair geometry ----------------
__global__ void pair_geom_kernel(const float* __restrict__ frac,
                                 const int* __restrict__ pinf,
                                 const float* __restrict__ ltl,
                                 float* __restrict__ fdP,
                                 float* __restrict__ udP)
{
    int p = blockIdx.x * blockDim.x + threadIdx.x;
    if (p >= NP) return;
    const int4 pv = ((const int4*)pinf)[p];
    int s = pv.x, d = pv.y, g = pv.x / NPG;
    float f[3];
#pragma unroll
    for (int i = 0; i < 3; i++) {
        float z = TWO_PI_F * (frac[d * 3 + i] - frac[s * 3 + i]);
        f[i] = atan2f(sinf(z), cosf(z)) * (1.0f / TWO_PI_F);
        fdP[p * 3 + i] = f[i];
    }
    float dt[3];
#pragma unroll
    for (int i = 0; i < 3; i++)
        dt[i] = ltl[g * 9 + i * 3 + 0] * f[0] + ltl[g * 9 + i * 3 + 1] * f[1] + ltl[g * 9 + i * 3 + 2] * f[2];
    float nrm = sqrtf(dt[0] * dt[0] + dt[1] * dt[1] + dt[2] * dt[2]) + 1e-12f;
#pragma unroll
    for (int i = 0; i < 3; i++) udP[p * 3 + i] = dt[i] / nrm;
}

// ---------------- pair fourier embedding ----------------
__global__ void fembP_kernel(const float* __restrict__ fdP,
                             float* __restrict__ sinP, float* __restrict__ cosP)
{
    int idx = blockIdx.x * blockDim.x + threadIdx.x;
    if (idx >= NP * 384) return;
    int p = idx / 384, r = idx - p * 384;
    int d = r >> 7, k = r & 127;
    float v = fdP[p * 3 + d] * (TWO_PI_F * (float)k);
    float s, c;
    sincosf(v, &s, &c);
    sinP[(size_t)p * 384 + r] = f2tf(s);
    cosP[(size_t)p * 384 + r] = f2tf(c);
}

// ---------------- tvec ----------------
__global__ void tvec_kernel(const float* __restrict__ Wtime, const float* __restrict__ Wlat,
                            float* __restrict__ tvec)
{
    int c = blockIdx.x * blockDim.x + threadIdx.x;
    if (c >= HD) return;
    float acc = 0.f;
    for (int k = 0; k < TD; k++) acc = fmaf(Wtime[k], Wlat[(HD + k) * HD + c], acc);
    tvec[c] = acc;
}

// ---------------- initial node embedding ----------------
__global__ void h0_kernel(const int* __restrict__ at, const int* __restrict__ n2g,
                          const float* __restrict__ t, const float* __restrict__ wnl,
                          const float* __restrict__ tvec, float* __restrict__ h)
{
    int idx = blockIdx.x * blockDim.x + threadIdx.x;
    if (idx >= NN * HD) return;
    int n = idx >> 9, c = idx & 511;
    int a = at[n] - 1;
    a = max(0, min(NA - 1, a));
    h[idx] = wnl[a * HD + c] + t[n2g[n]] * tvec[c];
}

// ---------------- per-(layer,graph) edge bias ----------------
__global__ void gbias_kernel(const float* __restrict__ We1, const float* __restrict__ Wnum,
                             const float* __restrict__ be1, const float* __restrict__ lp,
                             const int* __restrict__ numat, float* __restrict__ gb)
{
    int l = blockIdx.x / NB, b = blockIdx.x - l * NB;
    int c = threadIdx.x;
    const float* W = We1 + (size_t)l * EINR * HD;
    float acc = be1[l * HD + c];
#pragma unroll
    for (int k = 0; k < 6; k++) acc = fmaf(lp[b * 6 + k], W[(size_t)(1027 + k) * HD + c], acc);
    int na = numat[b] - 1;
    if (na >= 0 && na < NA) {
        const float* nav = Wnum + ((size_t)l * NA + na) * HD;
        for (int k = 0; k < HD; k++) acc = fmaf(nav[k], W[(size_t)(1801 + k) * HD + c], acc);
    }
    gb[(size_t)(l * NB + b) * HD + c] = acc;
}

// ---------------- layernorm (writes hn; optionally cat-left + zero cat-right) ---
__global__ void ln_kernel(const float* __restrict__ x, const float* __restrict__ g,
                          const float* __restrict__ bta, float* __restrict__ y,
                          float* __restrict__ y2, int rnd)
{
    int n = blockIdx.x, tid = threadIdx.x;
    const float* xr = x + (size_t)n * HD;
    float v0 = xr[tid], v1 = xr[tid + 256];
    float s = v0 + v1, q = v0 * v0 + v1 * v1;
#pragma unroll
    for (int o = 16; o > 0; o >>= 1) {
        s += __shfl_xor_sync(0xffffffffu, s, o);
        q += __shfl_xor_sync(0xffffffffu, q, o);
    }
    __shared__ float rs[8], rq[8], st[2];
    int w = tid >> 5;
    if ((tid & 31) == 0) { rs[w] = s; rq[w] = q; }
    __syncthreads();
    if (tid == 0) {
        float S = 0.f, Q = 0.f;
#pragma unroll
        for (int i = 0; i < 8; i++) { S += rs[i]; Q += rq[i]; }
        float mu = S * (1.0f / HD);
        float var = Q * (1.0f / HD) - mu * mu;
        st[0] = mu;
        st[1] = rsqrtf(var + 1e-5f);
    }
    __syncthreads();
    float mu = st[0], r = st[1];
    float o0 = (v0 - mu) * r * g[tid] + bta[tid];
    float o1 = (v1 - mu) * r * g[tid + 256] + bta[tid + 256];
    if (rnd) { o0 = f2tf(o0); o1 = f2tf(o1); }
    y[(size_t)n * HD + tid]       = o0;
    y[(size_t)n * HD + tid + 256] = o1;
    if (y2) {
        y2[(size_t)n * 2 * HD + tid]        = o0;
        y2[(size_t)n * 2 * HD + tid + 256]  = o1;
        y2[(size_t)n * 2 * HD + 512 + tid]  = 0.f;   // zero agg half
        y2[(size_t)n * 2 * HD + 768 + tid]  = 0.f;
    }
}

// ---------------- round aggregated cat half to tf32 ----------------
__global__ void roundcat_kernel(float* __restrict__ cat)
{
    int idx = blockIdx.x * blockDim.x + threadIdx.x;   // NN*HD
    int n = idx >> 9, c = idx & 511;
    size_t o = (size_t)n * 1024 + 512 + c;
    cat[o] = f2tf(cat[o]);
}

// ---------------- final heads ----------------
__global__ void posv_kernel(const float* __restrict__ hn, const float* __restrict__ Wc,
                            float* __restrict__ out)
{
    int idx = blockIdx.x * blockDim.x + threadIdx.x;
    if (idx >= NN * 3) return;
    int n = idx / 3, j = idx - n * 3;
    float acc = 0.f;
    for (int c = 0; c < HD; c++) acc = fmaf(hn[(size_t)n * HD + c], Wc[c * 3 + j], acc);
    out[idx] = acc;
}

__global__ void pool_kernel(const float* __restrict__ hn, const int* __restrict__ numat,
                            float* __restrict__ pool)
{
    int idx = blockIdx.x * blockDim.x + threadIdx.x;
    if (idx >= NB * HD) return;
    int b = idx >> 9, c = idx & 511;
    float s = 0.f;
#pragma unroll
    for (int i = 0; i < NPG; i++) s += hn[(size_t)(b * NPG + i) * HD + c];
    pool[(size_t)b * 2 * HD + c]      = s / (float)numat[b];
    pool[(size_t)b * 2 * HD + HD + c] = s;
}

__global__ void cellv_kernel(const float* __restrict__ pool, const float* __restrict__ Wlo,
                             const float* __restrict__ blo, float* __restrict__ out)
{
    int idx = blockIdx.x * blockDim.x + threadIdx.x;
    if (idx >= NB * 6) return;
    int b = idx / 6, j = idx - b * 6;
    float acc = blo[j];
    for (int k = 0; k < 2 * HD; k++) acc = fmaf(pool[(size_t)b * 2 * HD + k], Wlo[k * 6 + j], acc);
    out[idx] = acc;
}

// ---------------- host ----------------
extern "C" void kernel_launch(void* const* d_in, const int* in_sizes, int n_in,
                              void* d_out, int out_size)
{
    int I_at, I_na, I_n2g, base;
    if (in_sizes[3] == NN) {
        I_at = 3; I_na = 4; I_n2g = 5; base = 8;
    } else {
        base = 3; I_at = 22; I_na = 23; I_n2g = 24;
    }
    const float* t       = (const float*)d_in[0];
    const float* frac    = (const float*)d_in[1];
    const float* lp      = (const float*)d_in[2];
    const int*   at      = (const int*)d_in[I_at];
    const int*   numat   = (const int*)d_in[I_na];
    const int*   n2g     = (const int*)d_in[I_n2g];
    const float* Wnode   = (const float*)d_in[base + 0];
    const float* Wtime   = (const float*)d_in[base + 1];
    const float* Wlat    = (const float*)d_in[base + 2];
    const float* lng     = (const float*)d_in[base + 3];
    const float* lnb     = (const float*)d_in[base + 4];
    const float* We1     = (const float*)d_in[base + 5];
    const float* be1     = (const float*)d_in[base + 6];
    const float* We2     = (const float*)d_in[base + 7];
    const float* be2     = (const float*)d_in[base + 8];
    const float* Wn1     = (const float*)d_in[base + 9];
    const float* bn1     = (const float*)d_in[base + 10];
    const float* Wn2     = (const float*)d_in[base + 11];
    const float* bn2     = (const float*)d_in[base + 12];
    const float* Wnum    = (const float*)d_in[base + 13];
    const float* flng    = (const float*)d_in[base + 14];
    const float* flnb    = (const float*)d_in[base + 15];
    const float* Wcoord  = (const float*)d_in[base + 16];
    const float* Wlo     = (const float*)d_in[base + 17];
    const float* blo     = (const float*)d_in[base + 18];
    float* out = (float*)d_out;

    float *p_wtf, *p_wsm, *p_ltl, *p_fdP, *p_udP, *p_sinP, *p_cosP, *p_S,
          *p_gb, *p_wnl, *p_tvec, *p_h, *p_hn, *p_ns, *p_act1,
          *p_cat, *p_t1, *p_pool;
    int* p_pinf;
    cudaGetSymbolAddress((void**)&p_wtf,  d_wtf);
    cudaGetSymbolAddress((void**)&p_wsm,  d_wsm);
    cudaGetSymbolAddress((void**)&p_ltl,  d_ltl);
    cudaGetSymbolAddress((void**)&p_pinf, d_pinf);
    cudaGetSymbolAddress((void**)&p_fdP,  d_fdP);
    cudaGetSymbolAddress((void**)&p_udP,  d_udP);
    cudaGetSymbolAddress((void**)&p_sinP, d_sinP);
    cudaGetSymbolAddress((void**)&p_cosP, d_cosP);
    cudaGetSymbolAddress((void**)&p_S,    d_S);
    cudaGetSymbolAddress((void**)&p_gb,   d_gbias);
    cudaGetSymbolAddress((void**)&p_wnl,  d_wnl);
    cudaGetSymbolAddress((void**)&p_tvec, d_tvec);
    cudaGetSymbolAddress((void**)&p_h,    d_h);
    cudaGetSymbolAddress((void**)&p_hn,   d_hn);
    cudaGetSymbolAddress((void**)&p_ns,   d_ns);
    cudaGetSymbolAddress((void**)&p_act1, d_act1);
    cudaGetSymbolAddress((void**)&p_cat,  d_cat);
    cudaGetSymbolAddress((void**)&p_t1,   d_t1);
    cudaGetSymbolAddress((void**)&p_pool, d_pool);

    const int* nI = nullptr;
    const float* nF = nullptr;

    cudaFuncSetAttribute(tcgemm<0,0>, cudaFuncAttributeMaxDynamicSharedMemorySize, SMEM_BYTES);
    cudaFuncSetAttribute(tcgemm<4,1>, cudaFuncAttributeMaxDynamicSharedMemorySize, SMEM_BYTES);
    cudaFuncSetAttribute(tcgemm<5,0>, cudaFuncAttributeMaxDynamicSharedMemorySize, SMEM_BYTES);
    cudaFuncSetAttribute(tcgemm<1,1>, cudaFuncAttributeMaxDynamicSharedMemorySize, SMEM_BYTES);
    cudaFuncSetAttribute(tcgemm<3,0>, cudaFuncAttributeMaxDynamicSharedMemorySize, SMEM_BYTES);

    // ---- setup ----
    pack_weights<<<(int)(((size_t)NLY * WLS + 255) / 256), 256>>>(We1, We2, Wn1, Wn2, p_wtf);
    pack_small<<<(51200 + 262144 + 255) / 256, 256>>>(Wnode, Wlat, p_wsm);
    lattice_kernel<<<1, 64>>>(lp, p_ltl);
    pairgen_kernel<<<(NP + 127) / 128, 128>>>(p_pinf);
    pair_geom_kernel<<<(NP + 127) / 128, 128>>>(frac, p_pinf, p_ltl, p_fdP, p_udP);
    fembP_kernel<<<(NP * 384) / 256, 256>>>(p_fdP, p_sinP, p_cosP);
    tcgemm<0, 0><<<dim3(HD / 128, 1), 256, SMEM_BYTES>>>(NA, HD, HD,
        p_wsm, HD, p_wsm + 51200, HD, nF, p_wnl, HD, nI, nI, nF, nF, nF, nF);
    tvec_kernel<<<2, 256>>>(Wtime, Wlat, p_tvec);
    h0_kernel<<<(NN * HD) / 256, 256>>>(at, n2g, t, p_wnl, p_tvec, p_h);
    gbias_kernel<<<NLY * NB, HD>>>(We1, Wnum, be1, lp, numat, p_gb);

    // ---- layers ----
    for (int l = 0; l < NLY; l++) {
        const float* W = p_wtf + (size_t)l * WLS;
        ln_kernel<<<NN, 256>>>(p_h, lng + l * HD, lnb + l * HD, p_hn, p_cat, 1);
        tcgemm<0, 0><<<dim3(1024 / 128, NN / 128), 256, SMEM_BYTES>>>(NN, 1024, HD,
            p_hn, HD, W + OFF_SD, 1024, nF, p_ns, 1024, nI, nI, nF, nF, nF, nF);
        tcgemm<0, 0><<<dim3(HD / 128, NP / 128), 256, SMEM_BYTES>>>(NP, HD, 384,
            p_sinP, 384, W + OFF_FE, HD, nF, p_S, HD, nI, nI, nF, nF, nF, nF);
        tcgemm<4, 1><<<dim3(HD / 128, NP / 128), 256, SMEM_BYTES>>>(NP, HD, 384,
            p_cosP, 384, W + OFF_FE + (size_t)384 * HD, HD,
            p_S, p_act1, HD,
            p_pinf, nI, p_udP, We1 + (size_t)l * EINR * HD,
            p_gb + (size_t)l * NB * HD, p_ns);
        // e2 GEMM with fused per-node aggregation (atomics into cat)
        tcgemm<5, 0><<<dim3(HD / 128, NE / 128), 256, SMEM_BYTES>>>(NE, HD, HD,
            p_act1, HD, W + OFF_E2, HD, be2 + l * HD, p_cat, 0, nI, nI, nF, nF, nF, nF);
        roundcat_kernel<<<(NN * HD) / 256, 256>>>(p_cat);
        tcgemm<1, 1><<<dim3(HD / 128, NN / 128), 256, SMEM_BYTES>>>(NN, HD, 2 * HD,
            p_cat, 2 * HD, W + OFF_N1, HD, bn1 + l * HD, p_t1, HD, nI, nI, nF, nF, nF, nF);
        tcgemm<3, 0><<<dim3(HD / 128, NN / 128), 256, SMEM_BYTES>>>(NN, HD, HD,
            p_t1, HD, W + OFF_N2, HD, bn2 + l * HD, p_h, HD, nI, nI, nF, nF, nF, nF);
    }

    // ---- heads ----
    ln_kernel<<<NN, 256>>>(p_h, flng, flnb, p_hn, (float*)nullptr, 0);
    posv_kernel<<<(NN * 3 + 127) / 128, 128>>>(p_hn, Wcoord, out);
    pool_kernel<<<(NB * HD) / 256, 256>>>(p_hn, numat, p_pool);
    cellv_kernel<<<(NB * 6 + 127) / 128, 128>>>(p_pool, Wlo, blo, out + NN * 3);
}

// round 10
// speedup vs baseline: 1.0561x; 1.0561x over previous
#include <cuda_runtime.h>
#include <math.h>
#include <stdint.h>

// ---------------- problem constants ----------------
#define NB   64
#define NPG  20
#define NN   1280
#define NE   24320
#define NP   12160          // unordered pairs = NE/2
#define HD   512
#define NLY  6
#define TD   256
#define NA   100
#define EINR 2313
#define TWO_PI_F 6.2831853071795864769f

// packed weight layout per layer (floats)
#define OFF_SD 0            // 512 x 1024  (src|dst merged)
#define OFF_FE 524288       // 768 x 512   (rows 0..383 = sin, 384..767 = cos)
#define OFF_E2 917504       // 512 x 512
#define OFF_N1 1179648      // 1024 x 512
#define OFF_N2 1703936      // 512 x 512
#define WLS    1966080

// ---------------- scratch ----------------
__device__ float d_wtf [(size_t)NLY * WLS];
__device__ float d_wsm [51200 + 262144];
__device__ float d_ltl [NB * 9];
__device__ int   d_pinf[NP * 4];
__device__ float d_fdP [NP * 3];
__device__ float d_udP [NP * 3];
__device__ float d_sinP[(size_t)NP * 384];
__device__ float d_cosP[(size_t)NP * 384];
__device__ float d_S   [(size_t)NP * HD];
__device__ float d_gbias[NLY * NB * HD];
__device__ float d_wnl [128 * HD];
__device__ float d_tvec[HD];
__device__ float d_h   [NN * HD];
__device__ float d_hn  [NN * HD];
__device__ float d_ns  [NN * 1024];
__device__ float d_act1[(size_t)NE * HD];
__device__ float d_cat [NN * 2 * HD];
__device__ float d_t1  [NN * HD];
__device__ float d_pool[NB * 2 * HD];

__device__ __forceinline__ float siluf(float x) { return x / (1.0f + expf(-x)); }

__device__ __forceinline__ float f2tf(float x) {
    unsigned u;
    asm("cvt.rna.tf32.f32 %0, %1;" : "=r"(u) : "f"(x));
    return __uint_as_float(u);
}

__device__ __forceinline__ void mma4(float* d, const float* a, const float* b) {
    asm volatile(
        "mma.sync.aligned.m16n8k8.row.col.f32.tf32.tf32.f32 "
        "{%0,%1,%2,%3},{%4,%5,%6,%7},{%8,%9},{%0,%1,%2,%3};\n"
        : "+f"(d[0]), "+f"(d[1]), "+f"(d[2]), "+f"(d[3])
        : "r"(__float_as_uint(a[0])), "r"(__float_as_uint(a[1])),
          "r"(__float_as_uint(a[2])), "r"(__float_as_uint(a[3])),
          "r"(__float_as_uint(b[0])), "r"(__float_as_uint(b[1])));
}

__device__ __forceinline__ void cp16(uint32_t smem, const void* gptr, bool pred) {
    int sz = pred ? 16 : 0;
    asm volatile("cp.async.cg.shared.global [%0], [%1], 16, %2;\n"
                 :: "r"(smem), "l"(gptr), "r"(sz));
}
#define CP_COMMIT() asm volatile("cp.async.commit_group;\n")
#define CP_WAIT1()  asm volatile("cp.async.wait_group 1;\n")

// smem element-offset helpers (swizzled) — R4/R7-proven
__device__ __forceinline__ int aoff(int r, int k) {
    return r * 16 + ((((k >> 2) ^ ((r >> 1) & 3)) << 2) | (k & 3));
}
__device__ __forceinline__ int boff(int k, int n) {
    return k * 128 + ((((n >> 2) ^ ((k & 3) << 1)) << 2) | (n & 3));
}

// ================= TF32 cp.async pipelined GEMM, 128x128 tile (R7 core) ====
// MODE 0: C = acc ; 1: C = silu(acc+bias) ; 3: C += silu(acc+bias)
// MODE 4: pair epilogue (writes both directed edges into act1)
// MODE 5: fused aggregation: atomicAdd(cat[node, 512+n], silu(acc+bias)/19)
template<int MODE, int RND>
__global__ void __launch_bounds__(256, 2)
tcgemm(int M, int N, int K,
       const float* __restrict__ A, int lda,
       const float* __restrict__ B, int ldb,
       const float* __restrict__ bias,
       float* __restrict__ C, int ldc,
       const int* __restrict__ ei, const int* __restrict__ e2g,
       const float* __restrict__ ud, const float* __restrict__ W0,
       const float* __restrict__ gb, const float* __restrict__ nsd)
{
    __shared__ float sA[3][128 * 16];
    __shared__ float sB[3][16 * 128];

    const int tid  = threadIdx.x;
    const int lane = tid & 31, wid = tid >> 5;
    const int wm   = wid & 1,  wn  = wid >> 1;
    const int g    = lane >> 2, tg = lane & 3;
    const int bm   = blockIdx.y * 128, bn = blockIdx.x * 128;

    const int ar0 = tid >> 2,          as0 = tid & 3;
    const int ar1 = (tid + 256) >> 2,  as1 = tid & 3;
    const int bk0 = tid >> 5,          bg0 = tid & 31;
    const int bk1 = bk0 + 8,           bg1 = bg0;

    uint32_t sAb = (uint32_t)__cvta_generic_to_shared(&sA[0][0]);
    uint32_t sBb = (uint32_t)__cvta_generic_to_shared(&sB[0][0]);
    const uint32_t dA0 = (uint32_t)(ar0 * 16 + ((as0 ^ ((ar0 >> 1) & 3)) << 2)) * 4;
    const uint32_t dA1 = (uint32_t)(ar1 * 16 + ((as1 ^ ((ar1 >> 1) & 3)) << 2)) * 4;
    const uint32_t dB0 = (uint32_t)(bk0 * 128 + ((bg0 ^ ((bk0 & 3) << 1)) << 2)) * 4;
    const uint32_t dB1 = (uint32_t)(bk1 * 128 + ((bg1 ^ ((bk1 & 3) << 1)) << 2)) * 4;
    const bool pa0 = (bm + ar0) < M;
    const bool pa1 = (bm + ar1) < M;

    auto issue = [&](int st, int kt) {
        uint32_t sa = sAb + st * (128 * 16 * 4);
        uint32_t sb = sBb + st * (16 * 128 * 4);
        cp16(sa + dA0, A + (size_t)(bm + ar0) * lda + kt + (as0 << 2), pa0);
        cp16(sa + dA1, A + (size_t)(bm + ar1) * lda + kt + (as1 << 2), pa1);
        cp16(sb + dB0, B + (size_t)(kt + bk0) * ldb + bn + (bg0 << 2), true);
        cp16(sb + dB1, B + (size_t)(kt + bk1) * ldb + bn + (bg1 << 2), true);
    };

    float acc[4][4][4];
#pragma unroll
    for (int i = 0; i < 4; i++)
#pragma unroll
        for (int j = 0; j < 4; j++)
#pragma unroll
            for (int r = 0; r < 4; r++) acc[i][j][r] = 0.f;

    const int T = K >> 4;
    issue(0, 0); CP_COMMIT();
    if (T > 1) issue(1, 16);
    CP_COMMIT();

    for (int it = 0; it < T; ++it) {
        CP_WAIT1();
        __syncthreads();
        if (it + 2 < T) issue((it + 2) % 3, (it + 2) << 4);
        CP_COMMIT();

        const float* sa = sA[it % 3];
        const float* sb = sB[it % 3];
#pragma unroll
        for (int ks = 0; ks < 2; ++ks) {
            const int k0 = ks * 8 + tg, k1 = k0 + 4;
            float a[4][4], b[4][2];
#pragma unroll
            for (int mi = 0; mi < 4; ++mi) {
                int r0 = wm * 64 + mi * 16 + g;
                a[mi][0] = sa[aoff(r0,     k0)];
                a[mi][1] = sa[aoff(r0 + 8, k0)];
                a[mi][2] = sa[aoff(r0,     k1)];
                a[mi][3] = sa[aoff(r0 + 8, k1)];
            }
#pragma unroll
            for (int ni = 0; ni < 4; ++ni) {
                int n = wn * 32 + ni * 8 + g;
                b[ni][0] = sb[boff(k0, n)];
                b[ni][1] = sb[boff(k1, n)];
            }
#pragma unroll
            for (int mi = 0; mi < 4; ++mi)
#pragma unroll
                for (int ni = 0; ni < 4; ++ni)
                    mma4(acc[mi][ni], a[mi], b[ni]);
        }
    }

    // epilogue
    const int mbase = bm + wm * 64;
    const int nbase = bn + wn * 32;
#pragma unroll
    for (int im = 0; im < 4; ++im) {
#pragma unroll
        for (int rh = 0; rh < 2; ++rh) {
            int m = mbase + im * 16 + rh * 8 + g;
            if (m >= M) continue;
            int ig = 0, jg = 0, ef = 0, er = 0, gph = 0, node = 0;
            float u0 = 0.f, u1 = 0.f, u2 = 0.f;
            if (MODE == 4) {
                const int4 pv = ((const int4*)ei)[m];
                ig = pv.x; jg = pv.y; ef = pv.z; er = pv.w;
                gph = ig / NPG;
                u0 = ud[m * 3 + 0]; u1 = ud[m * 3 + 1]; u2 = ud[m * 3 + 2];
            }
            if (MODE == 5) node = m / (NPG - 1);
#pragma unroll
            for (int ni = 0; ni < 4; ++ni) {
                int n = nbase + ni * 8 + tg * 2;
                float v0 = acc[im][ni][rh * 2 + 0];
                float v1 = acc[im][ni][rh * 2 + 1];
                if (MODE == 4) {
                    size_t sm = (size_t)m * HD + n;
                    float S0 = bias[sm], S1 = bias[sm + 1];
                    size_t go = (size_t)gph * HD + n;
                    float w0 = u0 * W0[n]     + u1 * W0[HD + n]     + u2 * W0[2 * HD + n];
                    float w1 = u0 * W0[n + 1] + u1 * W0[HD + n + 1] + u2 * W0[2 * HD + n + 1];
                    float b0 = v0 + gb[go], b1 = v1 + gb[go + 1];
                    size_t io = (size_t)ig * 1024 + n;
                    size_t jo = (size_t)jg * 1024 + n;
                    float zf0 = b0 + S0 + nsd[io]     + nsd[jo + 512]     + w0;
                    float zf1 = b1 + S1 + nsd[io + 1] + nsd[jo + 512 + 1] + w1;
                    float zr0 = b0 - S0 + nsd[jo]     + nsd[io + 512]     - w0;
                    float zr1 = b1 - S1 + nsd[jo + 1] + nsd[io + 512 + 1] - w1;
                    float* Cf = C + (size_t)ef * ldc + n;
                    float* Cr = C + (size_t)er * ldc + n;
                    Cf[0] = f2tf(siluf(zf0)); Cf[1] = f2tf(siluf(zf1));
                    Cr[0] = f2tf(siluf(zr0)); Cr[1] = f2tf(siluf(zr1));
                } else if (MODE == 5) {
                    float o0 = siluf(v0 + bias[n]) * (1.0f / (float)(NPG - 1));
                    float o1 = siluf(v1 + bias[n + 1]) * (1.0f / (float)(NPG - 1));
                    float* Cp = C + (size_t)node * 1024 + 512 + n;
                    atomicAdd(Cp,     o0);
                    atomicAdd(Cp + 1, o1);
                } else {
                    float* Cp = C + (size_t)m * ldc + n;
                    float o0, o1;
                    if (MODE == 0) { o0 = v0; o1 = v1; }
                    else if (MODE == 1) {
                        o0 = siluf(v0 + bias[n]); o1 = siluf(v1 + bias[n + 1]);
                    } else {  // MODE 3
                        o0 = Cp[0] + siluf(v0 + bias[n]);
                        o1 = Cp[1] + siluf(v1 + bias[n + 1]);
                    }
                    if (RND) { o0 = f2tf(o0); o1 = f2tf(o1); }
                    Cp[0] = o0; Cp[1] = o1;
                }
            }
        }
    }
}

// ---------------- weight pack + round ----------------
__global__ void pack_weights(const float* __restrict__ We1, const float* __restrict__ We2,
                             const float* __restrict__ Wn1, const float* __restrict__ Wn2,
                             float* __restrict__ out)
{
    size_t idx = (size_t)blockIdx.x * blockDim.x + threadIdx.x;
    if (idx >= (size_t)NLY * WLS) return;
    int l = (int)(idx / WLS);
    size_t r = idx - (size_t)l * WLS;
    float v;
    if (r < OFF_FE) {
        int k = (int)(r >> 10), c = (int)(r & 1023);
        int srow = (c < 512) ? (3 + k) : (515 + k);
        v = We1[((size_t)l * EINR + srow) * HD + (c & 511)];
    } else if (r < OFF_E2) {
        size_t q = r - OFF_FE;
        v = We1[((size_t)l * EINR + 1033 + (q >> 9)) * HD + (q & 511)];
    } else if (r < OFF_N1) {
        v = We2[(size_t)l * HD * HD + (r - OFF_E2)];
    } else if (r < OFF_N2) {
        v = Wn1[(size_t)l * 2 * HD * HD + (r - OFF_N1)];
    } else {
        v = Wn2[(size_t)l * HD * HD + (r - OFF_N2)];
    }
    out[idx] = f2tf(v);
}

__global__ void pack_small(const float* __restrict__ Wnode, const float* __restrict__ Wlat,
                           float* __restrict__ out)
{
    int idx = blockIdx.x * blockDim.x + threadIdx.x;
    if (idx >= 51200 + 262144) return;
    float v = (idx < 51200) ? Wnode[idx] : Wlat[idx - 51200];
    out[idx] = f2tf(v);
}

// ---------------- lattice ----------------
__global__ void lattice_kernel(const float* __restrict__ lp, float* __restrict__ ltl)
{
    int b = blockIdx.x * blockDim.x + threadIdx.x;
    if (b >= NB) return;
    const float LMn[3] = {1.575442910194397f, 1.7017393112182617f, 1.9781638383865356f};
    const float LSd[3] = {0.24437622725963593f, 0.26526379585266113f, 0.3535512685775757f};
    float len[3], ang[3];
#pragma unroll
    for (int i = 0; i < 3; i++) len[i] = expf(lp[b * 6 + i] * LSd[i] + LMn[i]);
#pragma unroll
    for (int i = 0; i < 3; i++) {
        float x  = lp[b * 6 + 3 + i];
        float sg = 1.f / (1.f + expf(-x));
        ang[i]   = (59.9f + 60.2f * sg) * 0.017453292519943295f;
    }
    float c0 = cosf(ang[0]), c1 = cosf(ang[1]), c2 = cosf(ang[2]);
    float s0 = sinf(ang[0]), s1 = sinf(ang[1]);
    float val = (c0 * c1 - c2) / (s0 * s1);
    val = fminf(1.f, fmaxf(-1.f, val));
    float gs = acosf(val);
    float L[3][3];
    L[0][0] = len[0] * s1;             L[0][1] = 0.f;                    L[0][2] = len[0] * c1;
    L[1][0] = -len[1] * s0 * cosf(gs); L[1][1] = len[1] * s0 * sinf(gs); L[1][2] = len[1] * c0;
    L[2][0] = 0.f;                     L[2][1] = 0.f;                    L[2][2] = len[2];
#pragma unroll
    for (int i = 0; i < 3; i++)
#pragma unroll
        for (int j = 0; j < 3; j++)
            ltl[b * 9 + i * 3 + j] = L[i][0] * L[j][0] + L[i][1] * L[j][1] + L[i][2] * L[j][2];
}

// ---------------- pair index generation ----------------
__global__ void pairgen_kernel(int* __restrict__ pinf)
{
    int p = blockIdx.x * blockDim.x + threadIdx.x;
    if (p >= NP) return;
    int g = p / 190, pl = p - g * 190;
    int i = 0, rem = pl;
    while (rem >= (NPG - 1) - i) { rem -= (NPG - 1) - i; i++; }
    int j = i + 1 + rem;
    int ig = g * NPG + i, jg = g * NPG + j;
    int4 v;
    v.x = ig; v.y = jg;
    v.z = ig * (NPG - 1) + (j - 1);
    v.w = jg * (NPG - 1) + i;
    ((int4*)pinf)[p] = v;
}

// ---------------- per-pair geometry ----------------
__global__ void pair_geom_kernel(const float* __restrict__ frac,
                                 const int* __restrict__ pinf,
                                 const float* __restrict__ ltl,
                                 float* __restrict__ fdP,
                                 float* __restrict__ udP)
{
    int p = blockIdx.x * blockDim.x + threadIdx.x;
    if (p >= NP) return;
    const int4 pv = ((const int4*)pinf)[p];
    int s = pv.x, d = pv.y, g = pv.x / NPG;
    float f[3];
#pragma unroll
    for (int i = 0; i < 3; i++) {
        float z = TWO_PI_F * (frac[d * 3 + i] - frac[s * 3 + i]);
        f[i] = atan2f(sinf(z), cosf(z)) * (1.0f / TWO_PI_F);
        fdP[p * 3 + i] = f[i];
    }
    float dt[3];
#pragma unroll
    for (int i = 0; i < 3; i++)
        dt[i] = ltl[g * 9 + i * 3 + 0] * f[0] + ltl[g * 9 + i * 3 + 1] * f[1] + ltl[g * 9 + i * 3 + 2] * f[2];
    float nrm = sqrtf(dt[0] * dt[0] + dt[1] * dt[1] + dt[2] * dt[2]) + 1e-12f;
#pragma unroll
    for (int i = 0; i < 3; i++) udP[p * 3 + i] = dt[i] / nrm;
}

// ---------------- pair fourier embedding ----------------
__global__ void fembP_kernel(const float* __restrict__ fdP,
                             float* __restrict__ sinP, float* __restrict__ cosP)
{
    int idx = blockIdx.x * blockDim.x + threadIdx.x;
    if (idx >= NP * 384) return;
    int p = idx / 384, r = idx - p * 384;
    int d = r >> 7, k = r & 127;
    float v = fdP[p * 3 + d] * (TWO_PI_F * (float)k);
    float s, c;
    sincosf(v, &s, &c);
    sinP[(size_t)p * 384 + r] = f2tf(s);
    cosP[(size_t)p * 384 + r] = f2tf(c);
}

// ---------------- tvec ----------------
__global__ void tvec_kernel(const float* __restrict__ Wtime, const float* __restrict__ Wlat,
                            float* __restrict__ tvec)
{
    int c = blockIdx.x * blockDim.x + threadIdx.x;
    if (c >= HD) return;
    float acc = 0.f;
    for (int k = 0; k < TD; k++) acc = fmaf(Wtime[k], Wlat[(HD + k) * HD + c], acc);
    tvec[c] = acc;
}

// ---------------- initial node embedding ----------------
__global__ void h0_kernel(const int* __restrict__ at, const int* __restrict__ n2g,
                          const float* __restrict__ t, const float* __restrict__ wnl,
                          const float* __restrict__ tvec, float* __restrict__ h)
{
    int idx = blockIdx.x * blockDim.x + threadIdx.x;
    if (idx >= NN * HD) return;
    int n = idx >> 9, c = idx & 511;
    int a = at[n] - 1;
    a = max(0, min(NA - 1, a));
    h[idx] = wnl[a * HD + c] + t[n2g[n]] * tvec[c];
}

// ---------------- per-(layer,graph) edge bias ----------------
__global__ void gbias_kernel(const float* __restrict__ We1, const float* __restrict__ Wnum,
                             const float* __restrict__ be1, const float* __restrict__ lp,
                             const int* __restrict__ numat, float* __restrict__ gb)
{
    int l = blockIdx.x / NB, b = blockIdx.x - l * NB;
    int c = threadIdx.x;
    const float* W = We1 + (size_t)l * EINR * HD;
    float acc = be1[l * HD + c];
#pragma unroll
    for (int k = 0; k < 6; k++) acc = fmaf(lp[b * 6 + k], W[(size_t)(1027 + k) * HD + c], acc);
    int na = numat[b] - 1;
    if (na >= 0 && na < NA) {
        const float* nav = Wnum + ((size_t)l * NA + na) * HD;
        for (int k = 0; k < HD; k++) acc = fmaf(nav[k], W[(size_t)(1801 + k) * HD + c], acc);
    }
    gb[(size_t)(l * NB + b) * HD + c] = acc;
}

// ---------------- layernorm (writes hn; cat-left + zero agg half) ----------
__global__ void ln_kernel(const float* __restrict__ x, const float* __restrict__ g,
                          const float* __restrict__ bta, float* __restrict__ y,
                          float* __restrict__ y2, int rnd)
{
    int n = blockIdx.x, tid = threadIdx.x;
    const float* xr = x + (size_t)n * HD;
    float v0 = xr[tid], v1 = xr[tid + 256];
    float s = v0 + v1, q = v0 * v0 + v1 * v1;
#pragma unroll
    for (int o = 16; o > 0; o >>= 1) {
        s += __shfl_xor_sync(0xffffffffu, s, o);
        q += __shfl_xor_sync(0xffffffffu, q, o);
    }
    __shared__ float rs[8], rq[8], st[2];
    int w = tid >> 5;
    if ((tid & 31) == 0) { rs[w] = s; rq[w] = q; }
    __syncthreads();
    if (tid == 0) {
        float S = 0.f, Q = 0.f;
#pragma unroll
        for (int i = 0; i < 8; i++) { S += rs[i]; Q += rq[i]; }
        float mu = S * (1.0f / HD);
        float var = Q * (1.0f / HD) - mu * mu;
        st[0] = mu;
        st[1] = rsqrtf(var + 1e-5f);
    }
    __syncthreads();
    float mu = st[0], r = st[1];
    float o0 = (v0 - mu) * r * g[tid] + bta[tid];
    float o1 = (v1 - mu) * r * g[tid + 256] + bta[tid + 256];
    if (rnd) { o0 = f2tf(o0); o1 = f2tf(o1); }
    y[(size_t)n * HD + tid]       = o0;
    y[(size_t)n * HD + tid + 256] = o1;
    if (y2) {
        y2[(size_t)n * 2 * HD + tid]       = o0;
        y2[(size_t)n * 2 * HD + tid + 256] = o1;
        y2[(size_t)n * 2 * HD + 512 + tid] = 0.f;   // zero agg half for atomics
        y2[(size_t)n * 2 * HD + 768 + tid] = 0.f;
    }
}

// ---------------- round aggregated cat half to tf32 ----------------
__global__ void roundcat_kernel(float* __restrict__ cat)
{
    int idx = blockIdx.x * blockDim.x + threadIdx.x;   // NN*HD
    int n = idx >> 9, c = idx & 511;
    size_t o = (size_t)n * 1024 + 512 + c;
    cat[o] = f2tf(cat[o]);
}

// ---------------- final heads ----------------
__global__ void posv_kernel(const float* __restrict__ hn, const float* __restrict__ Wc,
                            float* __restrict__ out)
{
    int idx = blockIdx.x * blockDim.x + threadIdx.x;
    if (idx >= NN * 3) return;
    int n = idx / 3, j = idx - n * 3;
    float acc = 0.f;
    for (int c = 0; c < HD; c++) acc = fmaf(hn[(size_t)n * HD + c], Wc[c * 3 + j], acc);
    out[idx] = acc;
}

__global__ void pool_kernel(const float* __restrict__ hn, const int* __restrict__ numat,
                            float* __restrict__ pool)
{
    int idx = blockIdx.x * blockDim.x + threadIdx.x;
    if (idx >= NB * HD) return;
    int b = idx >> 9, c = idx & 511;
    float s = 0.f;
#pragma unroll
    for (int i = 0; i < NPG; i++) s += hn[(size_t)(b * NPG + i) * HD + c];
    pool[(size_t)b * 2 * HD + c]      = s / (float)numat[b];
    pool[(size_t)b * 2 * HD + HD + c] = s;
}

__global__ void cellv_kernel(const float* __restrict__ pool, const float* __restrict__ Wlo,
                             const float* __restrict__ blo, float* __restrict__ out)
{
    int idx = blockIdx.x * blockDim.x + threadIdx.x;
    if (idx >= NB * 6) return;
    int b = idx / 6, j = idx - b * 6;
    float acc = blo[j];
    for (int k = 0; k < 2 * HD; k++) acc = fmaf(pool[(size_t)b * 2 * HD + k], Wlo[k * 6 + j], acc);
    out[idx] = acc;
}

// ---------------- host ----------------
extern "C" void kernel_launch(void* const* d_in, const int* in_sizes, int n_in,
                              void* d_out, int out_size)
{
    int I_at, I_na, I_n2g, base;
    if (in_sizes[3] == NN) {
        I_at = 3; I_na = 4; I_n2g = 5; base = 8;
    } else {
        base = 3; I_at = 22; I_na = 23; I_n2g = 24;
    }
    const float* t       = (const float*)d_in[0];
    const float* frac    = (const float*)d_in[1];
    const float* lp      = (const float*)d_in[2];
    const int*   at      = (const int*)d_in[I_at];
    const int*   numat   = (const int*)d_in[I_na];
    const int*   n2g     = (const int*)d_in[I_n2g];
    const float* Wnode   = (const float*)d_in[base + 0];
    const float* Wtime   = (const float*)d_in[base + 1];
    const float* Wlat    = (const float*)d_in[base + 2];
    const float* lng     = (const float*)d_in[base + 3];
    const float* lnb     = (const float*)d_in[base + 4];
    const float* We1     = (const float*)d_in[base + 5];
    const float* be1     = (const float*)d_in[base + 6];
    const float* We2     = (const float*)d_in[base + 7];
    const float* be2     = (const float*)d_in[base + 8];
    const float* Wn1     = (const float*)d_in[base + 9];
    const float* bn1     = (const float*)d_in[base + 10];
    const float* Wn2     = (const float*)d_in[base + 11];
    const float* bn2     = (const float*)d_in[base + 12];
    const float* Wnum    = (const float*)d_in[base + 13];
    const float* flng    = (const float*)d_in[base + 14];
    const float* flnb    = (const float*)d_in[base + 15];
    const float* Wcoord  = (const float*)d_in[base + 16];
    const float* Wlo     = (const float*)d_in[base + 17];
    const float* blo     = (const float*)d_in[base + 18];
    float* out = (float*)d_out;

    float *p_wtf, *p_wsm, *p_ltl, *p_fdP, *p_udP, *p_sinP, *p_cosP, *p_S,
          *p_gb, *p_wnl, *p_tvec, *p_h, *p_hn, *p_ns, *p_act1,
          *p_cat, *p_t1, *p_pool;
    int* p_pinf;
    cudaGetSymbolAddress((void**)&p_wtf,  d_wtf);
    cudaGetSymbolAddress((void**)&p_wsm,  d_wsm);
    cudaGetSymbolAddress((void**)&p_ltl,  d_ltl);
    cudaGetSymbolAddress((void**)&p_pinf, d_pinf);
    cudaGetSymbolAddress((void**)&p_fdP,  d_fdP);
    cudaGetSymbolAddress((void**)&p_udP,  d_udP);
    cudaGetSymbolAddress((void**)&p_sinP, d_sinP);
    cudaGetSymbolAddress((void**)&p_cosP, d_cosP);
    cudaGetSymbolAddress((void**)&p_S,    d_S);
    cudaGetSymbolAddress((void**)&p_gb,   d_gbias);
    cudaGetSymbolAddress((void**)&p_wnl,  d_wnl);
    cudaGetSymbolAddress((void**)&p_tvec, d_tvec);
    cudaGetSymbolAddress((void**)&p_h,    d_h);
    cudaGetSymbolAddress((void**)&p_hn,   d_hn);
    cudaGetSymbolAddress((void**)&p_ns,   d_ns);
    cudaGetSymbolAddress((void**)&p_act1, d_act1);
    cudaGetSymbolAddress((void**)&p_cat,  d_cat);
    cudaGetSymbolAddress((void**)&p_t1,   d_t1);
    cudaGetSymbolAddress((void**)&p_pool, d_pool);

    const int* nI = nullptr;
    const float* nF = nullptr;

    // ---- setup ----
    pack_weights<<<(int)(((size_t)NLY * WLS + 255) / 256), 256>>>(We1, We2, Wn1, Wn2, p_wtf);
    pack_small<<<(51200 + 262144 + 255) / 256, 256>>>(Wnode, Wlat, p_wsm);
    lattice_kernel<<<1, 64>>>(lp, p_ltl);
    pairgen_kernel<<<(NP + 127) / 128, 128>>>(p_pinf);
    pair_geom_kernel<<<(NP + 127) / 128, 128>>>(frac, p_pinf, p_ltl, p_fdP, p_udP);
    fembP_kernel<<<(NP * 384) / 256, 256>>>(p_fdP, p_sinP, p_cosP);
    tcgemm<0, 0><<<dim3(HD / 128, 1), 256>>>(NA, HD, HD,
        p_wsm, HD, p_wsm + 51200, HD, nF, p_wnl, HD, nI, nI, nF, nF, nF, nF);
    tvec_kernel<<<2, 256>>>(Wtime, Wlat, p_tvec);
    h0_kernel<<<(NN * HD) / 256, 256>>>(at, n2g, t, p_wnl, p_tvec, p_h);
    gbias_kernel<<<NLY * NB, HD>>>(We1, Wnum, be1, lp, numat, p_gb);

    // ---- layers ----
    for (int l = 0; l < NLY; l++) {
        const float* W = p_wtf + (size_t)l * WLS;
        ln_kernel<<<NN, 256>>>(p_h, lng + l * HD, lnb + l * HD, p_hn, p_cat, 1);
        // merged src|dst projection: (NN x 1024)
        tcgemm<0, 0><<<dim3(1024 / 128, NN / 128), 256>>>(NN, 1024, HD,
            p_hn, HD, W + OFF_SD, 1024, nF, p_ns, 1024, nI, nI, nF, nF, nF, nF);
        // S = sinP @ Ws
        tcgemm<0, 0><<<dim3(HD / 128, NP / 128), 256>>>(NP, HD, 384,
            p_sinP, 384, W + OFF_FE, HD, nF, p_S, HD, nI, nI, nF, nF, nF, nF);
        // C = cosP @ Wc with fused pair epilogue -> act1 (both directed edges)
        tcgemm<4, 1><<<dim3(HD / 128, NP / 128), 256>>>(NP, HD, 384,
            p_cosP, 384, W + OFF_FE + (size_t)384 * HD, HD,
            p_S, p_act1, HD,
            p_pinf, nI, p_udP, We1 + (size_t)l * EINR * HD,
            p_gb + (size_t)l * NB * HD, p_ns);
        // e2 GEMM with fused per-node aggregation (atomics into cat agg half)
        tcgemm<5, 0><<<dim3(HD / 128, NE / 128), 256>>>(NE, HD, HD,
            p_act1, HD, W + OFF_E2, HD, be2 + l * HD, p_cat, 0, nI, nI, nF, nF, nF, nF);
        roundcat_kernel<<<(NN * HD) / 256, 256>>>(p_cat);
        tcgemm<1, 1><<<dim3(HD / 128, NN / 128), 256>>>(NN, HD, 2 * HD,
            p_cat, 2 * HD, W + OFF_N1, HD, bn1 + l * HD, p_t1, HD, nI, nI, nF, nF, nF, nF);
        tcgemm<3, 0><<<dim3(HD / 128, NN / 128), 256>>>(NN, HD, HD,
            p_t1, HD, W + OFF_N2, HD, bn2 + l * HD, p_h, HD, nI, nI, nF, nF, nF, nF);
    }

    // ---- heads ----
    ln_kernel<<<NN, 256>>>(p_h, flng, flnb, p_hn, (float*)nullptr, 0);
    posv_kernel<<<(NN * 3 + 127) / 128, 128>>>(p_hn, Wcoord, out);
    pool_kernel<<<(NB * HD) / 256, 256>>>(p_hn, numat, p_pool);
    cellv_kernel<<<(NB * 6 + 127) / 128, 128>>>(p_pool, Wlo, blo, out + NN * 3);
}

// round 12
// speedup vs baseline: 1.5026x; 1.4228x over previous
#include <cuda_runtime.h>
#include <cuda_fp16.h>
#include <math.h>
#include <stdint.h>

// ---------------- problem constants ----------------
#define NB   64
#define NPG  20
#define NN   1280
#define NE   24320
#define NP   12160
#define HD   512
#define NLY  6
#define TD   256
#define NA   100
#define EINR 2313
#define TWO_PI_F 6.2831853071795864769f

// packed TRANSPOSED weight layout per layer ([N][K] row-major, halves)
#define OFF_SD  0            // 1024 x 512
#define OFF_FES 524288       // 512 x 384 (sin)
#define OFF_FEC 720896       // 512 x 384 (cos)
#define OFF_E2  917504       // 512 x 512
#define OFF_N1  1179648      // 512 x 1024
#define OFF_N2  1703936      // 512 x 512
#define WLS     1966080

// ---------------- scratch ----------------
__device__ __half d_wtf [(size_t)NLY * WLS];
__device__ __half d_wsm [51200 + 262144];        // Wnode [100][512], WlatT [512][512]
__device__ float  d_ltl [NB * 9];
__device__ int    d_pinf[NP * 4];
__device__ float  d_fdP [NP * 3];
__device__ float  d_udP [NP * 3];
__device__ __half d_sinP[(size_t)NP * 384];
__device__ __half d_cosP[(size_t)NP * 384];
__device__ float  d_S   [(size_t)NP * HD];
__device__ float  d_gbias[NLY * NB * HD];
__device__ float  d_wnl [128 * HD];
__device__ float  d_tvec[HD];
__device__ float  d_h   [NN * HD];
__device__ float  d_hn  [NN * HD];
__device__ __half d_hnh [NN * HD];
__device__ float  d_ns  [NN * 1024];
__device__ __half d_act1[(size_t)NE * HD];
__device__ __half d_e2  [(size_t)NE * HD];
__device__ __half d_cat [NN * 2 * HD];
__device__ __half d_t1  [NN * HD];
__device__ float  d_pool[NB * 2 * HD];

__device__ __forceinline__ float siluf(float x) { return x / (1.0f + expf(-x)); }

__device__ __forceinline__ void mmah(float* d, const uint32_t* a, const uint32_t* b) {
    asm volatile(
        "mma.sync.aligned.m16n8k16.row.col.f32.f16.f16.f32 "
        "{%0,%1,%2,%3},{%4,%5,%6,%7},{%8,%9},{%0,%1,%2,%3};\n"
        : "+f"(d[0]), "+f"(d[1]), "+f"(d[2]), "+f"(d[3])
        : "r"(a[0]), "r"(a[1]), "r"(a[2]), "r"(a[3]), "r"(b[0]), "r"(b[1]));
}

__device__ __forceinline__ void cp16(uint32_t smem, const void* gptr, bool pred) {
    int sz = pred ? 16 : 0;
    asm volatile("cp.async.cg.shared.global [%0], [%1], 16, %2;\n"
                 :: "r"(smem), "l"(gptr), "r"(sz));
}
#define CP_COMMIT() asm volatile("cp.async.commit_group;\n")
#define CP_WAIT1()  asm volatile("cp.async.wait_group 1;\n")

// swizzle: word w (0..15) of row r -> w ^ (((r>>1)&3)<<2)
__device__ __forceinline__ int frow(int r) { return ((r >> 1) & 3) << 2; }

// ================= FP16 cp.async pipelined GEMM, 128x128 tile =============
// C(MxN) = A(MxK:half) @ W^T (W: [N][K] half). K%32==0, N%128==0, M guarded.
// MODE 0: float C = acc
// MODE 1: half  C = silu(acc + bias)
// MODE 3: float C += silu(acc + bias)
// MODE 4: half  C: pair epilogue (bias = S fp32; writes fwd+rev edges)
template<int MODE>
__global__ void __launch_bounds__(256, 2)
hgemm(int M, int N, int K,
      const __half* __restrict__ A, int lda,
      const __half* __restrict__ B, int ldb,
      const float* __restrict__ bias,
      void* __restrict__ Cv, int ldc,
      const int* __restrict__ ei,
      const float* __restrict__ ud, const float* __restrict__ W0,
      const float* __restrict__ gb, const float* __restrict__ nsd)
{
    __shared__ uint32_t sA[3][128 * 16];   // 128 rows x 16 words (32 halves)
    __shared__ uint32_t sB[3][128 * 16];

    const int tid  = threadIdx.x;
    const int lane = tid & 31, wid = tid >> 5;
    const int wm   = wid & 1,  wn  = wid >> 1;
    const int g    = lane >> 2, tg = lane & 3;
    const int bm   = blockIdx.y * 128, bn = blockIdx.x * 128;

    // cp.async: 512 chunks per operand, 2 per thread
    const int r0c = tid >> 2,  q0 = tid & 3;
    const int r1c = r0c + 64,  q1 = q0;

    uint32_t sAb = (uint32_t)__cvta_generic_to_shared(&sA[0][0]);
    uint32_t sBb = (uint32_t)__cvta_generic_to_shared(&sB[0][0]);
    const uint32_t dA0 = (uint32_t)(r0c * 16 + ((q0 * 4) ^ frow(r0c))) * 4;
    const uint32_t dA1 = (uint32_t)(r1c * 16 + ((q1 * 4) ^ frow(r1c))) * 4;
    const bool pa0 = (bm + r0c) < M;
    const bool pa1 = (bm + r1c) < M;

    auto issue = [&](int st, int kt) {
        uint32_t sa = sAb + st * (128 * 16 * 4);
        uint32_t sb = sBb + st * (128 * 16 * 4);
        cp16(sa + dA0, A + (size_t)(bm + r0c) * lda + kt + q0 * 8, pa0);
        cp16(sa + dA1, A + (size_t)(bm + r1c) * lda + kt + q1 * 8, pa1);
        cp16(sb + dA0, B + (size_t)(bn + r0c) * ldb + kt + q0 * 8, true);
        cp16(sb + dA1, B + (size_t)(bn + r1c) * ldb + kt + q1 * 8, true);
    };

    float acc[4][4][4];
#pragma unroll
    for (int i = 0; i < 4; i++)
#pragma unroll
        for (int j = 0; j < 4; j++)
#pragma unroll
            for (int r = 0; r < 4; r++) acc[i][j][r] = 0.f;

    const int T = K >> 5;
    issue(0, 0); CP_COMMIT();
    if (T > 1) issue(1, 32);
    CP_COMMIT();

    for (int it = 0; it < T; ++it) {
        CP_WAIT1();
        __syncthreads();
        if (it + 2 < T) issue((it + 2) % 3, (it + 2) << 5);
        CP_COMMIT();

        const uint32_t* sa = sA[it % 3];
        const uint32_t* sb = sB[it % 3];
#pragma unroll
        for (int s = 0; s < 2; ++s) {
            const int w0 = s * 8 + tg, w1 = w0 + 4;
            uint32_t a[4][4], b[4][2];
#pragma unroll
            for (int mi = 0; mi < 4; ++mi) {
                int ra = wm * 64 + mi * 16 + g;
                int rb = ra + 8;
                a[mi][0] = sa[ra * 16 + (w0 ^ frow(ra))];
                a[mi][1] = sa[rb * 16 + (w0 ^ frow(rb))];
                a[mi][2] = sa[ra * 16 + (w1 ^ frow(ra))];
                a[mi][3] = sa[rb * 16 + (w1 ^ frow(rb))];
            }
#pragma unroll
            for (int ni = 0; ni < 4; ++ni) {
                int n = wn * 32 + ni * 8 + g;
                b[ni][0] = sb[n * 16 + (w0 ^ frow(n))];
                b[ni][1] = sb[n * 16 + (w1 ^ frow(n))];
            }
#pragma unroll
            for (int mi = 0; mi < 4; ++mi)
#pragma unroll
                for (int ni = 0; ni < 4; ++ni)
                    mmah(acc[mi][ni], a[mi], b[ni]);
        }
    }

    // epilogue (C layout of m16n8: rows g,g+8; cols tg*2, tg*2+1)
    const int mbase = bm + wm * 64;
    const int nbase = bn + wn * 32;
    float*  Cf = (float*)Cv;
    __half* Ch = (__half*)Cv;
#pragma unroll
    for (int im = 0; im < 4; ++im) {
#pragma unroll
        for (int rh = 0; rh < 2; ++rh) {
            int m = mbase + im * 16 + rh * 8 + g;
            if (m >= M) continue;
            int ig = 0, jg = 0, ef = 0, er = 0, gph = 0;
            float u0 = 0.f, u1 = 0.f, u2 = 0.f;
            if (MODE == 4) {
                const int4 pv = ((const int4*)ei)[m];
                ig = pv.x; jg = pv.y; ef = pv.z; er = pv.w;
                gph = ig / NPG;
                u0 = ud[m * 3 + 0]; u1 = ud[m * 3 + 1]; u2 = ud[m * 3 + 2];
            }
#pragma unroll
            for (int ni = 0; ni < 4; ++ni) {
                int n = nbase + ni * 8 + tg * 2;
                float v0 = acc[im][ni][rh * 2 + 0];
                float v1 = acc[im][ni][rh * 2 + 1];
                if (MODE == 0) {
                    Cf[(size_t)m * ldc + n]     = v0;
                    Cf[(size_t)m * ldc + n + 1] = v1;
                } else if (MODE == 1) {
                    __half2 o = __floats2half2_rn(siluf(v0 + bias[n]),
                                                  siluf(v1 + bias[n + 1]));
                    *(__half2*)(Ch + (size_t)m * ldc + n) = o;
                } else if (MODE == 3) {
                    Cf[(size_t)m * ldc + n]     += siluf(v0 + bias[n]);
                    Cf[(size_t)m * ldc + n + 1] += siluf(v1 + bias[n + 1]);
                } else {  // MODE 4
                    size_t sm = (size_t)m * HD + n;
                    float S0 = bias[sm], S1 = bias[sm + 1];
                    size_t go = (size_t)gph * HD + n;
                    float w0 = u0 * W0[n]     + u1 * W0[HD + n]     + u2 * W0[2 * HD + n];
                    float w1 = u0 * W0[n + 1] + u1 * W0[HD + n + 1] + u2 * W0[2 * HD + n + 1];
                    float b0 = v0 + gb[go], b1 = v1 + gb[go + 1];
                    size_t io = (size_t)ig * 1024 + n;
                    size_t jo = (size_t)jg * 1024 + n;
                    float zf0 = b0 + S0 + nsd[io]     + nsd[jo + 512]     + w0;
                    float zf1 = b1 + S1 + nsd[io + 1] + nsd[jo + 512 + 1] + w1;
                    float zr0 = b0 - S0 + nsd[jo]     + nsd[io + 512]     - w0;
                    float zr1 = b1 - S1 + nsd[jo + 1] + nsd[io + 512 + 1] - w1;
                    *(__half2*)(Ch + (size_t)ef * ldc + n) =
                        __floats2half2_rn(siluf(zf0), siluf(zf1));
                    *(__half2*)(Ch + (size_t)er * ldc + n) =
                        __floats2half2_rn(siluf(zr0), siluf(zr1));
                }
            }
        }
    }
}

// ---------------- weight pack (TRANSPOSED [N][K]) -> half ----------------
__global__ void pack_weights(const float* __restrict__ We1, const float* __restrict__ We2,
                             const float* __restrict__ Wn1, const float* __restrict__ Wn2,
                             __half* __restrict__ out)
{
    size_t idx = (size_t)blockIdx.x * blockDim.x + threadIdx.x;
    if (idx >= (size_t)NLY * WLS) return;
    int l = (int)(idx / WLS);
    size_t r = idx - (size_t)l * WLS;
    float v;
    if (r < OFF_FES) {                       // SD: [1024][512]
        int n = (int)(r >> 9), k = (int)(r & 511);
        int srow = (n < 512) ? (3 + k) : (515 + k);
        v = We1[((size_t)l * EINR + srow) * HD + (n & 511)];
    } else if (r < OFF_FEC) {                // FE sin: [512][384]
        size_t q = r - OFF_FES;
        int n = (int)(q / 384), k = (int)(q % 384);
        v = We1[((size_t)l * EINR + 1033 + k) * HD + n];
    } else if (r < OFF_E2) {                 // FE cos: [512][384]
        size_t q = r - OFF_FEC;
        int n = (int)(q / 384), k = (int)(q % 384);
        v = We1[((size_t)l * EINR + 1417 + k) * HD + n];
    } else if (r < OFF_N1) {                 // E2: [512][512]
        size_t q = r - OFF_E2;
        int n = (int)(q >> 9), k = (int)(q & 511);
        v = We2[(size_t)l * HD * HD + (size_t)k * HD + n];
    } else if (r < OFF_N2) {                 // N1: [512][1024]
        size_t q = r - OFF_N1;
        int n = (int)(q >> 10), k = (int)(q & 1023);
        v = Wn1[(size_t)l * 2 * HD * HD + (size_t)k * HD + n];
    } else {                                 // N2: [512][512]
        size_t q = r - OFF_N2;
        int n = (int)(q >> 9), k = (int)(q & 511);
        v = Wn2[(size_t)l * HD * HD + (size_t)k * HD + n];
    }
    out[idx] = __float2half_rn(v);
}

__global__ void pack_small(const float* __restrict__ Wnode, const float* __restrict__ Wlat,
                           __half* __restrict__ out)
{
    int idx = blockIdx.x * blockDim.x + threadIdx.x;
    if (idx >= 51200 + 262144) return;
    float v;
    if (idx < 51200) v = Wnode[idx];
    else {
        int q = idx - 51200, n = q >> 9, k = q & 511;
        v = Wlat[(size_t)k * HD + n];        // transpose of Wlat[:512]
    }
    out[idx] = __float2half_rn(v);
}

// ---------------- lattice ----------------
__global__ void lattice_kernel(const float* __restrict__ lp, float* __restrict__ ltl)
{
    int b = blockIdx.x * blockDim.x + threadIdx.x;
    if (b >= NB) return;
    const float LMn[3] = {1.575442910194397f, 1.7017393112182617f, 1.9781638383865356f};
    const float LSd[3] = {0.24437622725963593f, 0.26526379585266113f, 0.3535512685775757f};
    float len[3], ang[3];
#pragma unroll
    for (int i = 0; i < 3; i++) len[i] = expf(lp[b * 6 + i] * LSd[i] + LMn[i]);
#pragma unroll
    for (int i = 0; i < 3; i++) {
        float x  = lp[b * 6 + 3 + i];
        float sg = 1.f / (1.f + expf(-x));
        ang[i]   = (59.9f + 60.2f * sg) * 0.017453292519943295f;
    }
    float c0 = cosf(ang[0]), c1 = cosf(ang[1]), c2 = cosf(ang[2]);
    float s0 = sinf(ang[0]), s1 = sinf(ang[1]);
    float val = (c0 * c1 - c2) / (s0 * s1);
    val = fminf(1.f, fmaxf(-1.f, val));
    float gs = acosf(val);
    float L[3][3];
    L[0][0] = len[0] * s1;             L[0][1] = 0.f;                    L[0][2] = len[0] * c1;
    L[1][0] = -len[1] * s0 * cosf(gs); L[1][1] = len[1] * s0 * sinf(gs); L[1][2] = len[1] * c0;
    L[2][0] = 0.f;                     L[2][1] = 0.f;                    L[2][2] = len[2];
#pragma unroll
    for (int i = 0; i < 3; i++)
#pragma unroll
        for (int j = 0; j < 3; j++)
            ltl[b * 9 + i * 3 + j] = L[i][0] * L[j][0] + L[i][1] * L[j][1] + L[i][2] * L[j][2];
}

// ---------------- pair index generation ----------------
__global__ void pairgen_kernel(int* __restrict__ pinf)
{
    int p = blockIdx.x * blockDim.x + threadIdx.x;
    if (p >= NP) return;
    int g = p / 190, pl = p - g * 190;
    int i = 0, rem = pl;
    while (rem >= (NPG - 1) - i) { rem -= (NPG - 1) - i; i++; }
    int j = i + 1 + rem;
    int ig = g * NPG + i, jg = g * NPG + j;
    int4 v;
    v.x = ig; v.y = jg;
    v.z = ig * (NPG - 1) + (j - 1);
    v.w = jg * (NPG - 1) + i;
    ((int4*)pinf)[p] = v;
}

// ---------------- per-pair geometry ----------------
__global__ void pair_geom_kernel(const float* __restrict__ frac,
                                 const int* __restrict__ pinf,
                                 const float* __restrict__ ltl,
                                 float* __restrict__ fdP,
                                 float* __restrict__ udP)
{
    int p = blockIdx.x * blockDim.x + threadIdx.x;
    if (p >= NP) return;
    const int4 pv = ((const int4*)pinf)[p];
    int s = pv.x, d = pv.y, g = pv.x / NPG;
    float f[3];
#pragma unroll
    for (int i = 0; i < 3; i++) {
        float z = TWO_PI_F * (frac[d * 3 + i] - frac[s * 3 + i]);
        f[i] = atan2f(sinf(z), cosf(z)) * (1.0f / TWO_PI_F);
        fdP[p * 3 + i] = f[i];
    }
    float dt[3];
#pragma unroll
    for (int i = 0; i < 3; i++)
        dt[i] = ltl[g * 9 + i * 3 + 0] * f[0] + ltl[g * 9 + i * 3 + 1] * f[1] + ltl[g * 9 + i * 3 + 2] * f[2];
    float nrm = sqrtf(dt[0] * dt[0] + dt[1] * dt[1] + dt[2] * dt[2]) + 1e-12f;
#pragma unroll
    for (int i = 0; i < 3; i++) udP[p * 3 + i] = dt[i] / nrm;
}

// ---------------- pair fourier embedding -> half ----------------
__global__ void fembP_kernel(const float* __restrict__ fdP,
                             __half* __restrict__ sinP, __half* __restrict__ cosP)
{
    int idx = blockIdx.x * blockDim.x + threadIdx.x;
    if (idx >= NP * 384) return;
    int p = idx / 384, r = idx - p * 384;
    int d = r >> 7, k = r & 127;
    float v = fdP[p * 3 + d] * (TWO_PI_F * (float)k);
    float s, c;
    sincosf(v, &s, &c);
    sinP[(size_t)p * 384 + r] = __float2half_rn(s);
    cosP[(size_t)p * 384 + r] = __float2half_rn(c);
}

// ---------------- tvec ----------------
__global__ void tvec_kernel(const float* __restrict__ Wtime, const float* __restrict__ Wlat,
                            float* __restrict__ tvec)
{
    int c = blockIdx.x * blockDim.x + threadIdx.x;
    if (c >= HD) return;
    float acc = 0.f;
    for (int k = 0; k < TD; k++) acc = fmaf(Wtime[k], Wlat[(HD + k) * HD + c], acc);
    tvec[c] = acc;
}

// ---------------- initial node embedding ----------------
__global__ void h0_kernel(const int* __restrict__ at, const int* __restrict__ n2g,
                          const float* __restrict__ t, const float* __restrict__ wnl,
                          const float* __restrict__ tvec, float* __restrict__ h)
{
    int idx = blockIdx.x * blockDim.x + threadIdx.x;
    if (idx >= NN * HD) return;
    int n = idx >> 9, c = idx & 511;
    int a = at[n] - 1;
    a = max(0, min(NA - 1, a));
    h[idx] = wnl[a * HD + c] + t[n2g[n]] * tvec[c];
}

// ---------------- per-(layer,graph) edge bias ----------------
__global__ void gbias_kernel(const float* __restrict__ We1, const float* __restrict__ Wnum,
                             const float* __restrict__ be1, const float* __restrict__ lp,
                             const int* __restrict__ numat, float* __restrict__ gb)
{
    int l = blockIdx.x / NB, b = blockIdx.x - l * NB;
    int c = threadIdx.x;
    const float* W = We1 + (size_t)l * EINR * HD;
    float acc = be1[l * HD + c];
#pragma unroll
    for (int k = 0; k < 6; k++) acc = fmaf(lp[b * 6 + k], W[(size_t)(1027 + k) * HD + c], acc);
    int na = numat[b] - 1;
    if (na >= 0 && na < NA) {
        const float* nav = Wnum + ((size_t)l * NA + na) * HD;
        for (int k = 0; k < HD; k++) acc = fmaf(nav[k], W[(size_t)(1801 + k) * HD + c], acc);
    }
    gb[(size_t)(l * NB + b) * HD + c] = acc;
}

// ---------------- layernorm: fp32 y (optional) + half hn + half cat-left ----
__global__ void ln_kernel(const float* __restrict__ x, const float* __restrict__ g,
                          const float* __restrict__ bta, float* __restrict__ y,
                          __half* __restrict__ yh, __half* __restrict__ cath)
{
    int n = blockIdx.x, tid = threadIdx.x;
    const float* xr = x + (size_t)n * HD;
    float v0 = xr[tid], v1 = xr[tid + 256];
    float s = v0 + v1, q = v0 * v0 + v1 * v1;
#pragma unroll
    for (int o = 16; o > 0; o >>= 1) {
        s += __shfl_xor_sync(0xffffffffu, s, o);
        q += __shfl_xor_sync(0xffffffffu, q, o);
    }
    __shared__ float rs[8], rq[8], st[2];
    int w = tid >> 5;
    if ((tid & 31) == 0) { rs[w] = s; rq[w] = q; }
    __syncthreads();
    if (tid == 0) {
        float S = 0.f, Q = 0.f;
#pragma unroll
        for (int i = 0; i < 8; i++) { S += rs[i]; Q += rq[i]; }
        float mu = S * (1.0f / HD);
        float var = Q * (1.0f / HD) - mu * mu;
        st[0] = mu;
        st[1] = rsqrtf(var + 1e-5f);
    }
    __syncthreads();
    float mu = st[0], r = st[1];
    float o0 = (v0 - mu) * r * g[tid] + bta[tid];
    float o1 = (v1 - mu) * r * g[tid + 256] + bta[tid + 256];
    if (y) {
        y[(size_t)n * HD + tid]       = o0;
        y[(size_t)n * HD + tid + 256] = o1;
    }
    if (yh) {
        __half h0 = __float2half_rn(o0), h1 = __float2half_rn(o1);
        yh[(size_t)n * HD + tid]       = h0;
        yh[(size_t)n * HD + tid + 256] = h1;
        cath[(size_t)n * 2 * HD + tid]       = h0;
        cath[(size_t)n * 2 * HD + tid + 256] = h1;
    }
}

// ---------------- aggregate edges (half in, fp32 sum, half out) ----------
__global__ void aggregate_kernel(const __half* __restrict__ e2, __half* __restrict__ cat)
{
    int idx = blockIdx.x * blockDim.x + threadIdx.x;
    int n = idx >> 9, c = idx & 511;
    size_t base = (size_t)n * (NPG - 1) * HD + c;
    float s = 0.f;
#pragma unroll
    for (int j = 0; j < NPG - 1; j++) s += __half2float(e2[base + (size_t)j * HD]);
    cat[(size_t)n * 2 * HD + HD + c] = __float2half_rn(s * (1.0f / (float)(NPG - 1)));
}

// ---------------- final heads ----------------
__global__ void posv_kernel(const float* __restrict__ hn, const float* __restrict__ Wc,
                            float* __restrict__ out)
{
    int idx = blockIdx.x * blockDim.x + threadIdx.x;
    if (idx >= NN * 3) return;
    int n = idx / 3, j = idx - n * 3;
    float acc = 0.f;
    for (int c = 0; c < HD; c++) acc = fmaf(hn[(size_t)n * HD + c], Wc[c * 3 + j], acc);
    out[idx] = acc;
}

__global__ void pool_kernel(const float* __restrict__ hn, const int* __restrict__ numat,
                            float* __restrict__ pool)
{
    int idx = blockIdx.x * blockDim.x + threadIdx.x;
    if (idx >= NB * HD) return;
    int b = idx >> 9, c = idx & 511;
    float s = 0.f;
#pragma unroll
    for (int i = 0; i < NPG; i++) s += hn[(size_t)(b * NPG + i) * HD + c];
    pool[(size_t)b * 2 * HD + c]      = s / (float)numat[b];
    pool[(size_t)b * 2 * HD + HD + c] = s;
}

__global__ void cellv_kernel(const float* __restrict__ pool, const float* __restrict__ Wlo,
                             const float* __restrict__ blo, float* __restrict__ out)
{
    int idx = blockIdx.x * blockDim.x + threadIdx.x;
    if (idx >= NB * 6) return;
    int b = idx / 6, j = idx - b * 6;
    float acc = blo[j];
    for (int k = 0; k < 2 * HD; k++) acc = fmaf(pool[(size_t)b * 2 * HD + k], Wlo[k * 6 + j], acc);
    out[idx] = acc;
}

// ---------------- host ----------------
extern "C" void kernel_launch(void* const* d_in, const int* in_sizes, int n_in,
                              void* d_out, int out_size)
{
    int I_at, I_na, I_n2g, base;
    if (in_sizes[3] == NN) {
        I_at = 3; I_na = 4; I_n2g = 5; base = 8;
    } else {
        base = 3; I_at = 22; I_na = 23; I_n2g = 24;
    }
    const float* t       = (const float*)d_in[0];
    const float* frac    = (const float*)d_in[1];
    const float* lp      = (const float*)d_in[2];
    const int*   at      = (const int*)d_in[I_at];
    const int*   numat   = (const int*)d_in[I_na];
    const int*   n2g     = (const int*)d_in[I_n2g];
    const float* Wnode   = (const float*)d_in[base + 0];
    const float* Wtime   = (const float*)d_in[base + 1];
    const float* Wlat    = (const float*)d_in[base + 2];
    const float* lng     = (const float*)d_in[base + 3];
    const float* lnb     = (const float*)d_in[base + 4];
    const float* We1     = (const float*)d_in[base + 5];
    const float* be1     = (const float*)d_in[base + 6];
    const float* We2     = (const float*)d_in[base + 7];
    const float* be2     = (const float*)d_in[base + 8];
    const float* Wn1     = (const float*)d_in[base + 9];
    const float* bn1     = (const float*)d_in[base + 10];
    const float* Wn2     = (const float*)d_in[base + 11];
    const float* bn2     = (const float*)d_in[base + 12];
    const float* Wnum    = (const float*)d_in[base + 13];
    const float* flng    = (const float*)d_in[base + 14];
    const float* flnb    = (const float*)d_in[base + 15];
    const float* Wcoord  = (const float*)d_in[base + 16];
    const float* Wlo     = (const float*)d_in[base + 17];
    const float* blo     = (const float*)d_in[base + 18];
    float* out = (float*)d_out;

    __half *p_wtf, *p_wsm, *p_sinP, *p_cosP, *p_hnh, *p_act1, *p_e2, *p_cat, *p_t1;
    float *p_ltl, *p_fdP, *p_udP, *p_S, *p_gb, *p_wnl, *p_tvec, *p_h, *p_hn,
          *p_ns, *p_pool;
    int* p_pinf;
    cudaGetSymbolAddress((void**)&p_wtf,  d_wtf);
    cudaGetSymbolAddress((void**)&p_wsm,  d_wsm);
    cudaGetSymbolAddress((void**)&p_ltl,  d_ltl);
    cudaGetSymbolAddress((void**)&p_pinf, d_pinf);
    cudaGetSymbolAddress((void**)&p_fdP,  d_fdP);
    cudaGetSymbolAddress((void**)&p_udP,  d_udP);
    cudaGetSymbolAddress((void**)&p_sinP, d_sinP);
    cudaGetSymbolAddress((void**)&p_cosP, d_cosP);
    cudaGetSymbolAddress((void**)&p_S,    d_S);
    cudaGetSymbolAddress((void**)&p_gb,   d_gbias);
    cudaGetSymbolAddress((void**)&p_wnl,  d_wnl);
    cudaGetSymbolAddress((void**)&p_tvec, d_tvec);
    cudaGetSymbolAddress((void**)&p_h,    d_h);
    cudaGetSymbolAddress((void**)&p_hn,   d_hn);
    cudaGetSymbolAddress((void**)&p_hnh,  d_hnh);
    cudaGetSymbolAddress((void**)&p_ns,   d_ns);
    cudaGetSymbolAddress((void**)&p_act1, d_act1);
    cudaGetSymbolAddress((void**)&p_e2,   d_e2);
    cudaGetSymbolAddress((void**)&p_cat,  d_cat);
    cudaGetSymbolAddress((void**)&p_t1,   d_t1);
    cudaGetSymbolAddress((void**)&p_pool, d_pool);

    const int* nI = nullptr;
    const float* nF = nullptr;

    // ---- setup ----
    pack_weights<<<(int)(((size_t)NLY * WLS + 255) / 256), 256>>>(We1, We2, Wn1, Wn2, p_wtf);
    pack_small<<<(51200 + 262144 + 255) / 256, 256>>>(Wnode, Wlat, p_wsm);
    lattice_kernel<<<1, 64>>>(lp, p_ltl);
    pairgen_kernel<<<(NP + 127) / 128, 128>>>(p_pinf);
    pair_geom_kernel<<<(NP + 127) / 128, 128>>>(frac, p_pinf, p_ltl, p_fdP, p_udP);
    fembP_kernel<<<(NP * 384) / 256, 256>>>(p_fdP, p_sinP, p_cosP);
    hgemm<0><<<dim3(HD / 128, 1), 256>>>(NA, HD, HD,
        p_wsm, HD, p_wsm + 51200, HD, nF, p_wnl, HD, nI, nF, nF, nF, nF);
    tvec_kernel<<<2, 256>>>(Wtime, Wlat, p_tvec);
    h0_kernel<<<(NN * HD) / 256, 256>>>(at, n2g, t, p_wnl, p_tvec, p_h);
    gbias_kernel<<<NLY * NB, HD>>>(We1, Wnum, be1, lp, numat, p_gb);

    // ---- layers ----
    for (int l = 0; l < NLY; l++) {
        const __half* W = p_wtf + (size_t)l * WLS;
        ln_kernel<<<NN, 256>>>(p_h, lng + l * HD, lnb + l * HD,
                               (float*)nullptr, p_hnh, p_cat);
        // merged src|dst projection: NN x 1024 (fp32 out for epilogue gathers)
        hgemm<0><<<dim3(8, NN / 128), 256>>>(NN, 1024, HD,
            p_hnh, HD, W + OFF_SD, HD, nF, p_ns, 1024, nI, nF, nF, nF, nF);
        // S = sinP @ Ws^T  (fp32 out)
        hgemm<0><<<dim3(4, NP / 128), 256>>>(NP, HD, 384,
            p_sinP, 384, W + OFF_FES, 384, nF, p_S, HD, nI, nF, nF, nF, nF);
        // act1 = pair epilogue over cosP @ Wc^T  (half out, both directed edges)
        hgemm<4><<<dim3(4, NP / 128), 256>>>(NP, HD, 384,
            p_cosP, 384, W + OFF_FEC, 384, p_S, p_act1, HD,
            p_pinf, p_udP, We1 + (size_t)l * EINR * HD,
            p_gb + (size_t)l * NB * HD, p_ns);
        // e2 = silu(act1 @ We2^T + be2)  (half out)
        hgemm<1><<<dim3(4, NE / 128), 256>>>(NE, HD, HD,
            p_act1, HD, W + OFF_E2, HD, be2 + l * HD, p_e2, HD, nI, nF, nF, nF, nF);
        aggregate_kernel<<<(NN * HD) / 256, 256>>>(p_e2, p_cat);
        // t1 = silu(cat @ Wn1^T + bn1)  (half out)
        hgemm<1><<<dim3(4, NN / 128), 256>>>(NN, HD, 2 * HD,
            p_cat, 2 * HD, W + OFF_N1, 2 * HD, bn1 + l * HD, p_t1, HD, nI, nF, nF, nF, nF);
        // h += silu(t1 @ Wn2^T + bn2)  (fp32)
        hgemm<3><<<dim3(4, NN / 128), 256>>>(NN, HD, HD,
            p_t1, HD, W + OFF_N2, HD, bn2 + l * HD, p_h, HD, nI, nF, nF, nF, nF);
    }

    // ---- heads ----
    ln_kernel<<<NN, 256>>>(p_h, flng, flnb, p_hn, (__half*)nullptr, (__half*)nullptr);
    posv_kernel<<<(NN * 3 + 127) / 128, 128>>>(p_hn, Wcoord, out);
    pool_kernel<<<(NB * HD) / 256, 256>>>(p_hn, numat, p_pool);
    cellv_kernel<<<(NB * 6 + 127) / 128, 128>>>(p_pool, Wlo, blo, out + NN * 3);
}

// round 15
// speedup vs baseline: 1.5720x; 1.0462x over previous
#include <cuda_runtime.h>
#include <cuda_fp16.h>
#include <math.h>
#include <stdint.h>

// ---------------- problem constants ----------------
#define NB   64
#define NPG  20
#define NN   1280
#define NE   24320
#define NP   12160
#define HD   512
#define NLY  6
#define TD   256
#define NA   100
#define EINR 2313
#define TWO_PI_F 6.2831853071795864769f

// packed TRANSPOSED weight layout per layer ([N][K] row-major, halves)
#define OFF_SD  0
#define OFF_FES 524288
#define OFF_FEC 720896
#define OFF_E2  917504
#define OFF_N1  1179648
#define OFF_N2  1703936
#define WLS     1966080

// ---------------- scratch ----------------
__device__ __half d_wtf [(size_t)NLY * WLS];
__device__ __half d_wsm [51200 + 262144];
__device__ float  d_ltl [NB * 9];
__device__ int    d_pinf[NP * 4];
__device__ float  d_fdP [NP * 3];
__device__ float  d_udP [NP * 3];
__device__ __half d_sinP[(size_t)NP * 384];
__device__ __half d_cosP[(size_t)NP * 384];
__device__ float  d_S   [(size_t)NP * HD];
__device__ float  d_gbias[NLY * NB * HD];
__device__ float  d_wnl [128 * HD];
__device__ float  d_tvec[HD];
__device__ float  d_h   [NN * HD];
__device__ float  d_hn  [NN * HD];
__device__ __half d_hnh [NN * HD];
__device__ float  d_ns  [NN * 1024];
__device__ __half d_act1[(size_t)NE * HD];
__device__ __half d_e2  [(size_t)NE * HD];
__device__ __half d_cat [NN * 2 * HD];
__device__ __half d_t1  [NN * HD];
__device__ float  d_pool[NB * 2 * HD];

__device__ __forceinline__ float siluf(float x) { return x / (1.0f + expf(-x)); }

__device__ __forceinline__ void mmah(float* d, const uint32_t* a, const uint32_t* b) {
    asm volatile(
        "mma.sync.aligned.m16n8k16.row.col.f32.f16.f16.f32 "
        "{%0,%1,%2,%3},{%4,%5,%6,%7},{%8,%9},{%0,%1,%2,%3};\n"
        : "+f"(d[0]), "+f"(d[1]), "+f"(d[2]), "+f"(d[3])
        : "r"(a[0]), "r"(a[1]), "r"(a[2]), "r"(a[3]), "r"(b[0]), "r"(b[1]));
}

__device__ __forceinline__ void cp16(uint32_t smem, const void* gptr, bool pred) {
    int sz = pred ? 16 : 0;
    asm volatile("cp.async.cg.shared.global [%0], [%1], 16, %2;\n"
                 :: "r"(smem), "l"(gptr), "r"(sz));
}
#define CP_COMMIT() asm volatile("cp.async.commit_group;\n")
#define CP_WAIT1()  asm volatile("cp.async.wait_group 1;\n")

#define LDSM4(r0, r1, r2, r3, addr) \
    asm volatile("ldmatrix.sync.aligned.m8n8.x4.shared.b16 {%0,%1,%2,%3}, [%4];" \
        : "=r"(r0), "=r"(r1), "=r"(r2), "=r"(r3) : "r"(addr))

// swizzle: word w (0..15) of row r -> w ^ (((r>>1)&3)<<2)
__device__ __forceinline__ int frow(int r) { return ((r >> 1) & 3) << 2; }

// ================= FP16 cp.async pipelined GEMM, 128x128 tile =============
// C(MxN) = A(MxK:half) @ W^T (W: [N][K] half). K%32==0, N%128==0, M guarded.
// MODE 0: float C = acc ; 1: half C = silu(acc+bias) ; 3: float C += silu(acc+bias)
// MODE 4: half C: pair epilogue (bias = S fp32; writes fwd+rev edges)
template<int MODE>
__global__ void __launch_bounds__(256, 2)
hgemm(int M, int N, int K,
      const __half* __restrict__ A, int lda,
      const __half* __restrict__ B, int ldb,
      const float* __restrict__ bias,
      void* __restrict__ Cv, int ldc,
      const int* __restrict__ ei,
      const float* __restrict__ ud, const float* __restrict__ W0,
      const float* __restrict__ gb, const float* __restrict__ nsd)
{
    __shared__ uint32_t sA[3][128 * 16];
    __shared__ uint32_t sB[3][128 * 16];

    const int tid  = threadIdx.x;
    const int lane = tid & 31, wid = tid >> 5;
    const int wm   = wid & 1,  wn  = wid >> 1;
    const int g    = lane >> 2, tg = lane & 3;
    const int bm   = blockIdx.y * 128, bn = blockIdx.x * 128;

    // cp.async: 512 16B-chunks per operand, 2 per thread
    const int r0c = tid >> 2,  q0 = tid & 3;
    const int r1c = r0c + 64,  q1 = q0;

    uint32_t sAb = (uint32_t)__cvta_generic_to_shared(&sA[0][0]);
    uint32_t sBb = (uint32_t)__cvta_generic_to_shared(&sB[0][0]);
    const uint32_t dA0 = (uint32_t)(r0c * 16 + ((q0 * 4) ^ frow(r0c))) * 4;
    const uint32_t dA1 = (uint32_t)(r1c * 16 + ((q1 * 4) ^ frow(r1c))) * 4;
    const bool pa0 = (bm + r0c) < M;
    const bool pa1 = (bm + r1c) < M;

    auto issue = [&](int st, int kt) {
        uint32_t sa = sAb + st * (128 * 16 * 4);
        uint32_t sb = sBb + st * (128 * 16 * 4);
        cp16(sa + dA0, A + (size_t)(bm + r0c) * lda + kt + q0 * 8, pa0);
        cp16(sa + dA1, A + (size_t)(bm + r1c) * lda + kt + q1 * 8, pa1);
        cp16(sb + dA0, B + (size_t)(bn + r0c) * ldb + kt + q0 * 8, true);
        cp16(sb + dA1, B + (size_t)(bn + r1c) * ldb + kt + q1 * 8, true);
    };

    // ldmatrix per-lane addressing
    const int laA = lane & 15;              // A row within 16-row tile
    const int aq  = lane >> 4;              // A chunk parity
    const int lbB = (lane & 7) + ((lane >> 4) << 3);  // B row within 16
    const int bqB = (lane >> 3) & 1;        // B chunk parity
    int baseA[4], frA[4], baseB[2], frB[2];
#pragma unroll
    for (int mi = 0; mi < 4; ++mi) {
        int r = wm * 64 + mi * 16 + laA;
        baseA[mi] = r * 16;
        frA[mi]   = frow(r);
    }
#pragma unroll
    for (int np = 0; np < 2; ++np) {
        int r = wn * 32 + np * 16 + lbB;
        baseB[np] = r * 16;
        frB[np]   = frow(r);
    }

    float acc[4][4][4];
#pragma unroll
    for (int i = 0; i < 4; i++)
#pragma unroll
        for (int j = 0; j < 4; j++)
#pragma unroll
            for (int r = 0; r < 4; r++) acc[i][j][r] = 0.f;

    const int T = K >> 5;
    issue(0, 0); CP_COMMIT();
    if (T > 1) issue(1, 32);
    CP_COMMIT();

    for (int it = 0; it < T; ++it) {
        CP_WAIT1();
        __syncthreads();
        if (it + 2 < T) issue((it + 2) % 3, (it + 2) << 5);
        CP_COMMIT();

        uint32_t saB = sAb + (it % 3) * (128 * 16 * 4);
        uint32_t sbB = sBb + (it % 3) * (128 * 16 * 4);
#pragma unroll
        for (int s = 0; s < 2; ++s) {
            uint32_t a[4][4], b[4][2];
#pragma unroll
            for (int mi = 0; mi < 4; ++mi) {
                uint32_t addr = saB +
                    (uint32_t)(baseA[mi] + ((((2 * s + aq) << 2)) ^ frA[mi])) * 4;
                LDSM4(a[mi][0], a[mi][1], a[mi][2], a[mi][3], addr);
            }
#pragma unroll
            for (int np = 0; np < 2; ++np) {
                uint32_t addr = sbB +
                    (uint32_t)(baseB[np] + ((((2 * s + bqB) << 2)) ^ frB[np])) * 4;
                LDSM4(b[2 * np][0], b[2 * np][1], b[2 * np + 1][0], b[2 * np + 1][1], addr);
            }
#pragma unroll
            for (int mi = 0; mi < 4; ++mi)
#pragma unroll
                for (int ni = 0; ni < 4; ++ni)
                    mmah(acc[mi][ni], a[mi], b[ni]);
        }
    }

    // epilogue
    const int mbase = bm + wm * 64;
    const int nbase = bn + wn * 32;
    float*  Cf = (float*)Cv;
    __half* Ch = (__half*)Cv;
#pragma unroll
    for (int im = 0; im < 4; ++im) {
#pragma unroll
        for (int rh = 0; rh < 2; ++rh) {
            int m = mbase + im * 16 + rh * 8 + g;
            if (m >= M) continue;
            int ig = 0, jg = 0, ef = 0, er = 0, gph = 0;
            float u0 = 0.f, u1 = 0.f, u2 = 0.f;
            if (MODE == 4) {
                const int4 pv = ((const int4*)ei)[m];
                ig = pv.x; jg = pv.y; ef = pv.z; er = pv.w;
                gph = ig / NPG;
                u0 = ud[m * 3 + 0]; u1 = ud[m * 3 + 1]; u2 = ud[m * 3 + 2];
            }
#pragma unroll
            for (int ni = 0; ni < 4; ++ni) {
                int n = nbase + ni * 8 + tg * 2;
                float v0 = acc[im][ni][rh * 2 + 0];
                float v1 = acc[im][ni][rh * 2 + 1];
                if (MODE == 0) {
                    Cf[(size_t)m * ldc + n]     = v0;
                    Cf[(size_t)m * ldc + n + 1] = v1;
                } else if (MODE == 1) {
                    __half2 o = __floats2half2_rn(siluf(v0 + bias[n]),
                                                  siluf(v1 + bias[n + 1]));
                    *(__half2*)(Ch + (size_t)m * ldc + n) = o;
                } else if (MODE == 3) {
                    Cf[(size_t)m * ldc + n]     += siluf(v0 + bias[n]);
                    Cf[(size_t)m * ldc + n + 1] += siluf(v1 + bias[n + 1]);
                } else {  // MODE 4
                    size_t sm = (size_t)m * HD + n;
                    float S0 = bias[sm], S1 = bias[sm + 1];
                    size_t go = (size_t)gph * HD + n;
                    float w0 = u0 * W0[n]     + u1 * W0[HD + n]     + u2 * W0[2 * HD + n];
                    float w1 = u0 * W0[n + 1] + u1 * W0[HD + n + 1] + u2 * W0[2 * HD + n + 1];
                    float b0 = v0 + gb[go], b1 = v1 + gb[go + 1];
                    size_t io = (size_t)ig * 1024 + n;
                    size_t jo = (size_t)jg * 1024 + n;
                    float zf0 = b0 + S0 + nsd[io]     + nsd[jo + 512]     + w0;
                    float zf1 = b1 + S1 + nsd[io + 1] + nsd[jo + 512 + 1] + w1;
                    float zr0 = b0 - S0 + nsd[jo]     + nsd[io + 512]     - w0;
                    float zr1 = b1 - S1 + nsd[jo + 1] + nsd[io + 512 + 1] - w1;
                    *(__half2*)(Ch + (size_t)ef * ldc + n) =
                        __floats2half2_rn(siluf(zf0), siluf(zf1));
                    *(__half2*)(Ch + (size_t)er * ldc + n) =
                        __floats2half2_rn(siluf(zr0), siluf(zr1));
                }
            }
        }
    }
}

// ---------------- weight pack (TRANSPOSED [N][K]) -> half ----------------
__global__ void pack_weights(const float* __restrict__ We1, const float* __restrict__ We2,
                             const float* __restrict__ Wn1, const float* __restrict__ Wn2,
                             __half* __restrict__ out)
{
    size_t idx = (size_t)blockIdx.x * blockDim.x + threadIdx.x;
    if (idx >= (size_t)NLY * WLS) return;
    int l = (int)(idx / WLS);
    size_t r = idx - (size_t)l * WLS;
    float v;
    if (r < OFF_FES) {
        int n = (int)(r >> 9), k = (int)(r & 511);
        int srow = (n < 512) ? (3 + k) : (515 + k);
        v = We1[((size_t)l * EINR + srow) * HD + (n & 511)];
    } else if (r < OFF_FEC) {
        size_t q = r - OFF_FES;
        int n = (int)(q / 384), k = (int)(q % 384);
        v = We1[((size_t)l * EINR + 1033 + k) * HD + n];
    } else if (r < OFF_E2) {
        size_t q = r - OFF_FEC;
        int n = (int)(q / 384), k = (int)(q % 384);
        v = We1[((size_t)l * EINR + 1417 + k) * HD + n];
    } else if (r < OFF_N1) {
        size_t q = r - OFF_E2;
        int n = (int)(q >> 9), k = (int)(q & 511);
        v = We2[(size_t)l * HD * HD + (size_t)k * HD + n];
    } else if (r < OFF_N2) {
        size_t q = r - OFF_N1;
        int n = (int)(q >> 10), k = (int)(q & 1023);
        v = Wn1[(size_t)l * 2 * HD * HD + (size_t)k * HD + n];
    } else {
        size_t q = r - OFF_N2;
        int n = (int)(q >> 9), k = (int)(q & 511);
        v = Wn2[(size_t)l * HD * HD + (size_t)k * HD + n];
    }
    out[idx] = __float2half_rn(v);
}

__global__ void pack_small(const float* __restrict__ Wnode, const float* __restrict__ Wlat,
                           __half* __restrict__ out)
{
    int idx = blockIdx.x * blockDim.x + threadIdx.x;
    if (idx >= 51200 + 262144) return;
    float v;
    if (idx < 51200) v = Wnode[idx];
    else {
        int q = idx - 51200, n = q >> 9, k = q & 511;
        v = Wlat[(size_t)k * HD + n];
    }
    out[idx] = __float2half_rn(v);
}

// ---------------- lattice ----------------
__global__ void lattice_kernel(const float* __restrict__ lp, float* __restrict__ ltl)
{
    int b = blockIdx.x * blockDim.x + threadIdx.x;
    if (b >= NB) return;
    const float LMn[3] = {1.575442910194397f, 1.7017393112182617f, 1.9781638383865356f};
    const float LSd[3] = {0.24437622725963593f, 0.26526379585266113f, 0.3535512685775757f};
    float len[3], ang[3];
#pragma unroll
    for (int i = 0; i < 3; i++) len[i] = expf(lp[b * 6 + i] * LSd[i] + LMn[i]);
#pragma unroll
    for (int i = 0; i < 3; i++) {
        float x  = lp[b * 6 + 3 + i];
        float sg = 1.f / (1.f + expf(-x));
        ang[i]   = (59.9f + 60.2f * sg) * 0.017453292519943295f;
    }
    float c0 = cosf(ang[0]), c1 = cosf(ang[1]), c2 = cosf(ang[2]);
    float s0 = sinf(ang[0]), s1 = sinf(ang[1]);
    float val = (c0 * c1 - c2) / (s0 * s1);
    val = fminf(1.f, fmaxf(-1.f, val));
    float gs = acosf(val);
    float L[3][3];
    L[0][0] = len[0] * s1;             L[0][1] = 0.f;                    L[0][2] = len[0] * c1;
    L[1][0] = -len[1] * s0 * cosf(gs); L[1][1] = len[1] * s0 * sinf(gs); L[1][2] = len[1] * c0;
    L[2][0] = 0.f;                     L[2][1] = 0.f;                    L[2][2] = len[2];
#pragma unroll
    for (int i = 0; i < 3; i++)
#pragma unroll
        for (int j = 0; j < 3; j++)
            ltl[b * 9 + i * 3 + j] = L[i][0] * L[j][0] + L[i][1] * L[j][1] + L[i][2] * L[j][2];
}

// ---------------- pair index generation ----------------
__global__ void pairgen_kernel(int* __restrict__ pinf)
{
    int p = blockIdx.x * blockDim.x + threadIdx.x;
    if (p >= NP) return;
    int g = p / 190, pl = p - g * 190;
    int i = 0, rem = pl;
    while (rem >= (NPG - 1) - i) { rem -= (NPG - 1) - i; i++; }
    int j = i + 1 + rem;
    int ig = g * NPG + i, jg = g * NPG + j;
    int4 v;
    v.x = ig; v.y = jg;
    v.z = ig * (NPG - 1) + (j - 1);
    v.w = jg * (NPG - 1) + i;
    ((int4*)pinf)[p] = v;
}

// ---------------- per-pair geometry ----------------
__global__ void pair_geom_kernel(const float* __restrict__ frac,
                                 const int* __restrict__ pinf,
                                 const float* __restrict__ ltl,
                                 float* __restrict__ fdP,
                                 float* __restrict__ udP)
{
    int p = blockIdx.x * blockDim.x + threadIdx.x;
    if (p >= NP) return;
    const int4 pv = ((const int4*)pinf)[p];
    int s = pv.x, d = pv.y, g = pv.x / NPG;
    float f[3];
#pragma unroll
    for (int i = 0; i < 3; i++) {
        float z = TWO_PI_F * (frac[d * 3 + i] - frac[s * 3 + i]);
        f[i] = atan2f(sinf(z), cosf(z)) * (1.0f / TWO_PI_F);
        fdP[p * 3 + i] = f[i];
    }
    float dt[3];
#pragma unroll
    for (int i = 0; i < 3; i++)
        dt[i] = ltl[g * 9 + i * 3 + 0] * f[0] + ltl[g * 9 + i * 3 + 1] * f[1] + ltl[g * 9 + i * 3 + 2] * f[2];
    float nrm = sqrtf(dt[0] * dt[0] + dt[1] * dt[1] + dt[2] * dt[2]) + 1e-12f;
#pragma unroll
    for (int i = 0; i < 3; i++) udP[p * 3 + i] = dt[i] / nrm;
}

// ---------------- pair fourier embedding -> half ----------------
__global__ void fembP_kernel(const float* __restrict__ fdP,
                             __half* __restrict__ sinP, __half* __restrict__ cosP)
{
    int idx = blockIdx.x * blockDim.x + threadIdx.x;
    if (idx >= NP * 384) return;
    int p = idx / 384, r = idx - p * 384;
    int d = r >> 7, k = r & 127;
    float v = fdP[p * 3 + d] * (TWO_PI_F * (float)k);
    float s, c;
    sincosf(v, &s, &c);
    sinP[(size_t)p * 384 + r] = __float2half_rn(s);
    cosP[(size_t)p * 384 + r] = __float2half_rn(c);
}

// ---------------- tvec ----------------
__global__ void tvec_kernel(const float* __restrict__ Wtime, const float* __restrict__ Wlat,
                            float* __restrict__ tvec)
{
    int c = blockIdx.x * blockDim.x + threadIdx.x;
    if (c >= HD) return;
    float acc = 0.f;
    for (int k = 0; k < TD; k++) acc = fmaf(Wtime[k], Wlat[(HD + k) * HD + c], acc);
    tvec[c] = acc;
}

// ---------------- initial node embedding ----------------
__global__ void h0_kernel(const int* __restrict__ at, const int* __restrict__ n2g,
                          const float* __restrict__ t, const float* __restrict__ wnl,
                          const float* __restrict__ tvec, float* __restrict__ h)
{
    int idx = blockIdx.x * blockDim.x + threadIdx.x;
    if (idx >= NN * HD) return;
    int n = idx >> 9, c = idx & 511;
    int a = at[n] - 1;
    a = max(0, min(NA - 1, a));
    h[idx] = wnl[a * HD + c] + t[n2g[n]] * tvec[c];
}

// ---------------- per-(layer,graph) edge bias ----------------
__global__ void gbias_kernel(const float* __restrict__ We1, const float* __restrict__ Wnum,
                             const float* __restrict__ be1, const float* __restrict__ lp,
                             const int* __restrict__ numat, float* __restrict__ gb)
{
    int l = blockIdx.x / NB, b = blockIdx.x - l * NB;
    int c = threadIdx.x;
    const float* W = We1 + (size_t)l * EINR * HD;
    float acc = be1[l * HD + c];
#pragma unroll
    for (int k = 0; k < 6; k++) acc = fmaf(lp[b * 6 + k], W[(size_t)(1027 + k) * HD + c], acc);
    int na = numat[b] - 1;
    if (na >= 0 && na < NA) {
        const float* nav = Wnum + ((size_t)l * NA + na) * HD;
        for (int k = 0; k < HD; k++) acc = fmaf(nav[k], W[(size_t)(1801 + k) * HD + c], acc);
    }
    gb[(size_t)(l * NB + b) * HD + c] = acc;
}

// ---------------- layernorm ----------------
__global__ void ln_kernel(const float* __restrict__ x, const float* __restrict__ g,
                          const float* __restrict__ bta, float* __restrict__ y,
                          __half* __restrict__ yh, __half* __restrict__ cath)
{
    int n = blockIdx.x, tid = threadIdx.x;
    const float* xr = x + (size_t)n * HD;
    float v0 = xr[tid], v1 = xr[tid + 256];
    float s = v0 + v1, q = v0 * v0 + v1 * v1;
#pragma unroll
    for (int o = 16; o > 0; o >>= 1) {
        s += __shfl_xor_sync(0xffffffffu, s, o);
        q += __shfl_xor_sync(0xffffffffu, q, o);
    }
    __shared__ float rs[8], rq[8], st[2];
    int w = tid >> 5;
    if ((tid & 31) == 0) { rs[w] = s; rq[w] = q; }
    __syncthreads();
    if (tid == 0) {
        float S = 0.f, Q = 0.f;
#pragma unroll
        for (int i = 0; i < 8; i++) { S += rs[i]; Q += rq[i]; }
        float mu = S * (1.0f / HD);
        float var = Q * (1.0f / HD) - mu * mu;
        st[0] = mu;
        st[1] = rsqrtf(var + 1e-5f);
    }
    __syncthreads();
    float mu = st[0], r = st[1];
    float o0 = (v0 - mu) * r * g[tid] + bta[tid];
    float o1 = (v1 - mu) * r * g[tid + 256] + bta[tid + 256];
    if (y) {
        y[(size_t)n * HD + tid]       = o0;
        y[(size_t)n * HD + tid + 256] = o1;
    }
    if (yh) {
        __half h0 = __float2half_rn(o0), h1 = __float2half_rn(o1);
        yh[(size_t)n * HD + tid]       = h0;
        yh[(size_t)n * HD + tid + 256] = h1;
        cath[(size_t)n * 2 * HD + tid]       = h0;
        cath[(size_t)n * 2 * HD + tid + 256] = h1;
    }
}

// ---------------- aggregate edges (vectorized: uint4 = 8 halves) ----------
__global__ void aggregate_kernel(const __half* __restrict__ e2, __half* __restrict__ cat)
{
    int idx = blockIdx.x * blockDim.x + threadIdx.x;   // NN*64
    if (idx >= NN * 64) return;
    int n = idx >> 6, c8 = (idx & 63) << 3;
    float s[8];
#pragma unroll
    for (int e = 0; e < 8; e++) s[e] = 0.f;
    const uint4* base = (const uint4*)(e2 + (size_t)n * (NPG - 1) * HD + c8);
#pragma unroll
    for (int j = 0; j < NPG - 1; j++) {
        uint4 v = base[(size_t)j * (HD / 8)];
        const __half2* h2 = (const __half2*)&v;
#pragma unroll
        for (int e = 0; e < 4; e++) {
            float2 f = __half22float2(h2[e]);
            s[e * 2]     += f.x;
            s[e * 2 + 1] += f.y;
        }
    }
    uint4 o;
    __half2* oh = (__half2*)&o;
#pragma unroll
    for (int e = 0; e < 4; e++)
        oh[e] = __floats2half2_rn(s[e * 2] * (1.0f / (float)(NPG - 1)),
                                  s[e * 2 + 1] * (1.0f / (float)(NPG - 1)));
    *(uint4*)(cat + (size_t)n * 2 * HD + HD + c8) = o;
}

// ---------------- final heads ----------------
__global__ void posv_kernel(const float* __restrict__ hn, const float* __restrict__ Wc,
                            float* __restrict__ out)
{
    int idx = blockIdx.x * blockDim.x + threadIdx.x;
    if (idx >= NN * 3) return;
    int n = idx / 3, j = idx - n * 3;
    float acc = 0.f;
    for (int c = 0; c < HD; c++) acc = fmaf(hn[(size_t)n * HD + c], Wc[c * 3 + j], acc);
    out[idx] = acc;
}

__global__ void pool_kernel(const float* __restrict__ hn, const int* __restrict__ numat,
                            float* __restrict__ pool)
{
    int idx = blockIdx.x * blockDim.x + threadIdx.x;
    if (idx >= NB * HD) return;
    int b = idx >> 9, c = idx & 511;
    float s = 0.f;
#pragma unroll
    for (int i = 0; i < NPG; i++) s += hn[(size_t)(b * NPG + i) * HD + c];
    pool[(size_t)b * 2 * HD + c]      = s / (float)numat[b];
    pool[(size_t)b * 2 * HD + HD + c] = s;
}

__global__ void cellv_kernel(const float* __restrict__ pool, const float* __restrict__ Wlo,
                             const float* __restrict__ blo, float* __restrict__ out)
{
    int idx = blockIdx.x * blockDim.x + threadIdx.x;
    if (idx >= NB * 6) return;
    int b = idx / 6, j = idx - b * 6;
    float acc = blo[j];
    for (int k = 0; k < 2 * HD; k++) acc = fmaf(pool[(size_t)b * 2 * HD + k], Wlo[k * 6 + j], acc);
    out[idx] = acc;
}

// ---------------- host ----------------
extern "C" void kernel_launch(void* const* d_in, const int* in_sizes, int n_in,
                              void* d_out, int out_size)
{
    int I_at, I_na, I_n2g, base;
    if (in_sizes[3] == NN) {
        I_at = 3; I_na = 4; I_n2g = 5; base = 8;
    } else {
        base = 3; I_at = 22; I_na = 23; I_n2g = 24;
    }
    const float* t       = (const float*)d_in[0];
    const float* frac    = (const float*)d_in[1];
    const float* lp      = (const float*)d_in[2];
    const int*   at      = (const int*)d_in[I_at];
    const int*   numat   = (const int*)d_in[I_na];
    const int*   n2g     = (const int*)d_in[I_n2g];
    const float* Wnode   = (const float*)d_in[base + 0];
    const float* Wtime   = (const float*)d_in[base + 1];
    const float* Wlat    = (const float*)d_in[base + 2];
    const float* lng     = (const float*)d_in[base + 3];
    const float* lnb     = (const float*)d_in[base + 4];
    const float* We1     = (const float*)d_in[base + 5];
    const float* be1     = (const float*)d_in[base + 6];
    const float* We2     = (const float*)d_in[base + 7];
    const float* be2     = (const float*)d_in[base + 8];
    const float* Wn1     = (const float*)d_in[base + 9];
    const float* bn1     = (const float*)d_in[base + 10];
    const float* Wn2     = (const float*)d_in[base + 11];
    const float* bn2     = (const float*)d_in[base + 12];
    const float* Wnum    = (const float*)d_in[base + 13];
    const float* flng    = (const float*)d_in[base + 14];
    const float* flnb    = (const float*)d_in[base + 15];
    const float* Wcoord  = (const float*)d_in[base + 16];
    const float* Wlo     = (const float*)d_in[base + 17];
    const float* blo     = (const float*)d_in[base + 18];
    float* out = (float*)d_out;

    __half *p_wtf, *p_wsm, *p_sinP, *p_cosP, *p_hnh, *p_act1, *p_e2, *p_cat, *p_t1;
    float *p_ltl, *p_fdP, *p_udP, *p_S, *p_gb, *p_wnl, *p_tvec, *p_h, *p_hn,
          *p_ns, *p_pool;
    int* p_pinf;
    cudaGetSymbolAddress((void**)&p_wtf,  d_wtf);
    cudaGetSymbolAddress((void**)&p_wsm,  d_wsm);
    cudaGetSymbolAddress((void**)&p_ltl,  d_ltl);
    cudaGetSymbolAddress((void**)&p_pinf, d_pinf);
    cudaGetSymbolAddress((void**)&p_fdP,  d_fdP);
    cudaGetSymbolAddress((void**)&p_udP,  d_udP);
    cudaGetSymbolAddress((void**)&p_sinP, d_sinP);
    cudaGetSymbolAddress((void**)&p_cosP, d_cosP);
    cudaGetSymbolAddress((void**)&p_S,    d_S);
    cudaGetSymbolAddress((void**)&p_gb,   d_gbias);
    cudaGetSymbolAddress((void**)&p_wnl,  d_wnl);
    cudaGetSymbolAddress((void**)&p_tvec, d_tvec);
    cudaGetSymbolAddress((void**)&p_h,    d_h);
    cudaGetSymbolAddress((void**)&p_hn,   d_hn);
    cudaGetSymbolAddress((void**)&p_hnh,  d_hnh);
    cudaGetSymbolAddress((void**)&p_ns,   d_ns);
    cudaGetSymbolAddress((void**)&p_act1, d_act1);
    cudaGetSymbolAddress((void**)&p_e2,   d_e2);
    cudaGetSymbolAddress((void**)&p_cat,  d_cat);
    cudaGetSymbolAddress((void**)&p_t1,   d_t1);
    cudaGetSymbolAddress((void**)&p_pool, d_pool);

    const int* nI = nullptr;
    const float* nF = nullptr;

    // ---- setup ----
    pack_weights<<<(int)(((size_t)NLY * WLS + 255) / 256), 256>>>(We1, We2, Wn1, Wn2, p_wtf);
    pack_small<<<(51200 + 262144 + 255) / 256, 256>>>(Wnode, Wlat, p_wsm);
    lattice_kernel<<<1, 64>>>(lp, p_ltl);
    pairgen_kernel<<<(NP + 127) / 128, 128>>>(p_pinf);
    pair_geom_kernel<<<(NP + 127) / 128, 128>>>(frac, p_pinf, p_ltl, p_fdP, p_udP);
    fembP_kernel<<<(NP * 384) / 256, 256>>>(p_fdP, p_sinP, p_cosP);
    hgemm<0><<<dim3(HD / 128, 1), 256>>>(NA, HD, HD,
        p_wsm, HD, p_wsm + 51200, HD, nF, p_wnl, HD, nI, nF, nF, nF, nF);
    tvec_kernel<<<2, 256>>>(Wtime, Wlat, p_tvec);
    h0_kernel<<<(NN * HD) / 256, 256>>>(at, n2g, t, p_wnl, p_tvec, p_h);
    gbias_kernel<<<NLY * NB, HD>>>(We1, Wnum, be1, lp, numat, p_gb);

    // ---- layers ----
    for (int l = 0; l < NLY; l++) {
        const __half* W = p_wtf + (size_t)l * WLS;
        ln_kernel<<<NN, 256>>>(p_h, lng + l * HD, lnb + l * HD,
                               (float*)nullptr, p_hnh, p_cat);
        hgemm<0><<<dim3(8, NN / 128), 256>>>(NN, 1024, HD,
            p_hnh, HD, W + OFF_SD, HD, nF, p_ns, 1024, nI, nF, nF, nF, nF);
        hgemm<0><<<dim3(4, NP / 128), 256>>>(NP, HD, 384,
            p_sinP, 384, W + OFF_FES, 384, nF, p_S, HD, nI, nF, nF, nF, nF);
        hgemm<4><<<dim3(4, NP / 128), 256>>>(NP, HD, 384,
            p_cosP, 384, W + OFF_FEC, 384, p_S, p_act1, HD,
            p_pinf, p_udP, We1 + (size_t)l * EINR * HD,
            p_gb + (size_t)l * NB * HD, p_ns);
        hgemm<1><<<dim3(4, NE / 128), 256>>>(NE, HD, HD,
            p_act1, HD, W + OFF_E2, HD, be2 + l * HD, p_e2, HD, nI, nF, nF, nF, nF);
        aggregate_kernel<<<(NN * 64 + 255) / 256, 256>>>(p_e2, p_cat);
        hgemm<1><<<dim3(4, NN / 128), 256>>>(NN, HD, 2 * HD,
            p_cat, 2 * HD, W + OFF_N1, 2 * HD, bn1 + l * HD, p_t1, HD, nI, nF, nF, nF, nF);
        hgemm<3><<<dim3(4, NN / 128), 256>>>(NN, HD, HD,
            p_t1, HD, W + OFF_N2, HD, bn2 + l * HD, p_h, HD, nI, nF, nF, nF, nF);
    }

    // ---- heads ----
    ln_kernel<<<NN, 256>>>(p_h, flng, flnb, p_hn, (__half*)nullptr, (__half*)nullptr);
    posv_kernel<<<(NN * 3 + 127) / 128, 128>>>(p_hn, Wcoord, out);
    pool_kernel<<<(NB * HD) / 256, 256>>>(p_hn, numat, p_pool);
    cellv_kernel<<<(NB * 6 + 127) / 128, 128>>>(p_pool, Wlo, blo, out + NN * 3);
}